// round 11
// baseline (speedup 1.0000x reference)
#include <cuda_runtime.h>
#include <cuda_bf16.h>
#include <math.h>
#include <stdint.h>

#define BB 64
#define TT 31
#define EE 512
#define HH 1024
#define GG 4096
#define VV 32000
#define MPAD 2048
typedef __nv_bfloat16 bf;
typedef signed char s8;

// bf16 hi/lo (gbias / gx / steps — unchanged proven path)
__device__ __align__(16) bf g_WihH[(size_t)GG * 1536], g_WihL[(size_t)GG * 1536];
__device__ __align__(16) bf g_WhhH[(size_t)GG * HH], g_WhhL[(size_t)GG * HH];
__device__ __align__(16) bf g_ctxH[BB * HH], g_ctxL[BB * HH];
__device__ __align__(16) bf g_embH[(size_t)TT * BB * EE], g_embL[(size_t)TT * BB * EE];
__device__ __align__(16) bf g_hsH[(size_t)MPAD * HH], g_hsL[(size_t)MPAD * HH];
__device__ __align__(16) bf g_h0H[BB * HH], g_h0L[BB * HH];
// int8 two-digit operands for logits
__device__ __align__(16) s8 g_hsA1[(size_t)MPAD * HH], g_hsA2[(size_t)MPAD * HH];
__device__ __align__(16) s8 g_linB1[(size_t)VV * HH], g_linB2[(size_t)VV * HH];
__device__ float g_sv[VV];                 // per-vocab-row max|w|
__device__ float g_gbias[BB * GG];
__device__ float g_gx[(size_t)TT * BB * GG];
__device__ float g_c[BB * HH];

// ---------------------------------------------------------------------------
#define CP16(dst, src) asm volatile("cp.async.ca.shared.global [%0], [%1], 16;" :: "r"(dst), "l"(src) : "memory")
#define CP_COMMIT() asm volatile("cp.async.commit_group;" ::: "memory")
#define CP_WAIT0() asm volatile("cp.async.wait_group 0;" ::: "memory")
#define CP_WAIT1() asm volatile("cp.async.wait_group 1;" ::: "memory")

__device__ __forceinline__ unsigned s2u(const void* p) {
    return (unsigned)__cvta_generic_to_shared(p);
}
__device__ __forceinline__ void mma_bf16(float c[4], const unsigned a[4], const unsigned b[2]) {
    asm("mma.sync.aligned.m16n8k16.row.col.f32.bf16.bf16.f32 "
        "{%0,%1,%2,%3},{%4,%5,%6,%7},{%8,%9},{%0,%1,%2,%3};"
        : "+f"(c[0]), "+f"(c[1]), "+f"(c[2]), "+f"(c[3])
        : "r"(a[0]), "r"(a[1]), "r"(a[2]), "r"(a[3]), "r"(b[0]), "r"(b[1]));
}
__device__ __forceinline__ void mma_s8(int c[4], const unsigned a[4], const unsigned b[2]) {
    asm("mma.sync.aligned.m16n8k32.row.col.s32.s8.s8.s32 "
        "{%0,%1,%2,%3},{%4,%5,%6,%7},{%8,%9},{%0,%1,%2,%3};"
        : "+r"(c[0]), "+r"(c[1]), "+r"(c[2]), "+r"(c[3])
        : "r"(a[0]), "r"(a[1]), "r"(a[2]), "r"(a[3]), "r"(b[0]), "r"(b[1]));
}
__device__ __forceinline__ void split2(float x, float y, unsigned& hi, unsigned& lo) {
    bf hx = __float2bfloat16(x), hy = __float2bfloat16(y);
    __nv_bfloat162 H = __halves2bfloat162(hx, hy);
    __nv_bfloat162 L = __halves2bfloat162(__float2bfloat16(x - __bfloat162float(hx)),
                                          __float2bfloat16(y - __bfloat162float(hy)));
    hi = *(unsigned*)&H;
    lo = *(unsigned*)&L;
}

// ---------------------------------------------------------------------------
__global__ void k_init() {
    int i = blockIdx.x * blockDim.x + threadIdx.x;
    if (i < BB * HH) {
        g_h0H[i] = __float2bfloat16(0.f);
        g_h0L[i] = __float2bfloat16(0.f);
        g_c[i] = 0.f;
    }
    if (i < (MPAD - TT * BB) * HH) {
        size_t p = (size_t)TT * BB * HH + i;
        g_hsH[p] = __float2bfloat16(0.f);
        g_hsL[p] = __float2bfloat16(0.f);
        g_hsA1[p] = 0;
        g_hsA2[p] = 0;
    }
}

// fp32 -> bf16 hi/lo (W_ih, W_hh); 2 independent float4 per thread
__global__ void k_conv(const float4* __restrict__ S, uint2* __restrict__ H,
                       uint2* __restrict__ L, int n4) {
    int i = blockIdx.x * blockDim.x + threadIdx.x;
    int half = n4 >> 1;
    if (i >= half) return;
    float4 v0 = S[i];
    float4 v1 = S[i + half];
    uint2 h0, l0, h1, l1;
    split2(v0.x, v0.y, h0.x, l0.x);
    split2(v0.z, v0.w, h0.y, l0.y);
    split2(v1.x, v1.y, h1.x, l1.x);
    split2(v1.z, v1.w, h1.y, l1.y);
    H[i] = h0; L[i] = l0;
    H[i + half] = h1; L[i + half] = l1;
}

// per-row max|w| of lin_W (one warp per row)
__global__ void k_rowmax(const float* __restrict__ W) {
    int row = blockIdx.x * 8 + (threadIdx.x >> 5);
    int lane = threadIdx.x & 31;
    const float4* p = (const float4*)(W + (size_t)row * HH) + lane;
    float m = 0.f;
#pragma unroll
    for (int i = 0; i < 8; i++) {
        float4 v = p[i * 32];
        m = fmaxf(m, fmaxf(fmaxf(fabsf(v.x), fabsf(v.y)), fmaxf(fabsf(v.z), fabsf(v.w))));
    }
#pragma unroll
    for (int o = 16; o; o >>= 1) m = fmaxf(m, __shfl_xor_sync(0xffffffffu, m, o));
    if (lane == 0) g_sv[row] = m;
}

// lin_W -> two int8 digit planes: w ~= M_v * (q1*128 + q2) / 8192
__device__ __forceinline__ unsigned q4(float4 v, float sinv, unsigned& p2) {
    int q1[4], q2[4];
    float w[4] = {v.x, v.y, v.z, v.w};
#pragma unroll
    for (int j = 0; j < 4; j++) {
        float x = w[j] * sinv;
        q1[j] = __float2int_rn(x * 0.0078125f);
        q2[j] = __float2int_rn(fmaf(-128.f, (float)q1[j], x));
    }
    p2 = (unsigned)(q2[0] & 255) | ((unsigned)(q2[1] & 255) << 8) |
         ((unsigned)(q2[2] & 255) << 16) | ((unsigned)(q2[3] & 255) << 24);
    return (unsigned)(q1[0] & 255) | ((unsigned)(q1[1] & 255) << 8) |
           ((unsigned)(q1[2] & 255) << 16) | ((unsigned)(q1[3] & 255) << 24);
}
__global__ void k_qw(const float4* __restrict__ W, unsigned* __restrict__ B1,
                     unsigned* __restrict__ B2, int n4) {
    int i = blockIdx.x * blockDim.x + threadIdx.x;
    int half = n4 >> 1;
    if (i >= half) return;
#pragma unroll
    for (int rep = 0; rep < 2; rep++) {
        int idx = i + rep * half;
        float mv = g_sv[idx >> 8];               // 256 float4 per row
        float sinv = mv > 0.f ? 8192.f / mv : 0.f;
        unsigned p2;
        unsigned p1 = q4(W[idx], sinv, p2);
        B1[idx] = p1;
        B2[idx] = p2;
    }
}

__global__ void k_ctx(const float* __restrict__ features) {
    int b = blockIdx.x;
    for (int h = threadIdx.x; h < HH; h += blockDim.x) {
        const float* p = features + (size_t)b * 64 * HH + h;
        float s = 0.f;
#pragma unroll 8
        for (int l = 0; l < 64; l++) s += p[(size_t)l * HH];
        bf hi = __float2bfloat16(s);
        g_ctxH[b * HH + h] = hi;
        g_ctxL[b * HH + h] = __float2bfloat16(s - __bfloat162float(hi));
    }
}

__global__ void k_emb(const float* __restrict__ embed, const int* __restrict__ captions) {
    int v = blockIdx.x * blockDim.x + threadIdx.x;
    int m = v >> 7;
    int e4 = (v & 127) << 2;
    int t = m / 64, b = m % 64;
    int cap = captions[b * 32 + t];
    float4 val = *(const float4*)(embed + (size_t)cap * EE + e4);
    uint2 h, l;
    split2(val.x, val.y, h.x, l.x);
    split2(val.z, val.w, h.y, l.y);
    ((uint2*)g_embH)[((size_t)m * EE + e4) >> 2] = h;
    ((uint2*)g_embL)[((size_t)m * EE + e4) >> 2] = l;
}

// ---------------------------------------------------------------------------
// mma.sync bf16x3 GEMM for gbias / gx (proven config, unchanged)
template<int MODE>
__global__ __launch_bounds__(256) void k_mm(
    const bf* __restrict__ AH, const bf* __restrict__ AL, int lda,
    const bf* __restrict__ BH, const bf* __restrict__ BL, int ldb,
    float* __restrict__ C, int ldc, int K,
    const float* __restrict__ bias1, const float* __restrict__ bias2,
    const float* __restrict__ addM)
{
    __shared__ unsigned AsH[2][64][12], AsL[2][64][12];
    __shared__ unsigned BsH[2][128][12], BsL[2][128][12];
    const int tid = threadIdx.x;
    const int wid = tid >> 5, lane = tid & 31, g = lane >> 2, tig = lane & 3;
    const int wm = (wid & 1) * 32, wn = (wid >> 1) * 32;
    const int bm = blockIdx.y * 64, bn = blockIdx.x * 128;

    const int arow = tid >> 2, asel = (tid >> 1) & 1, achk = tid & 1;
    const bf* aSrc = (asel ? AL : AH) + (size_t)(bm + arow) * lda + achk * 8;
    unsigned aD[2] = { s2u(&(asel ? AsL : AsH)[0][arow][achk * 4]),
                       s2u(&(asel ? AsL : AsH)[1][arow][achk * 4]) };
    const int b0r = tid >> 2, b0s = (tid >> 1) & 1, b0c = tid & 1;
    const int id1 = tid + 256;
    const int b1r = id1 >> 2, b1s = (id1 >> 1) & 1, b1c = id1 & 1;
    const bf* bSrc0 = (b0s ? BL : BH) + (size_t)(bn + b0r) * ldb + b0c * 8;
    const bf* bSrc1 = (b1s ? BL : BH) + (size_t)(bn + b1r) * ldb + b1c * 8;
    unsigned b0D[2] = { s2u(&(b0s ? BsL : BsH)[0][b0r][b0c * 4]),
                        s2u(&(b0s ? BsL : BsH)[1][b0r][b0c * 4]) };
    unsigned b1D[2] = { s2u(&(b1s ? BsL : BsH)[0][b1r][b1c * 4]),
                        s2u(&(b1s ? BsL : BsH)[1][b1r][b1c * 4]) };

    float acc[2][4][4] = {};
    CP16(aD[0], aSrc); CP16(b0D[0], bSrc0); CP16(b1D[0], bSrc1); CP_COMMIT();

    const int KT = K >> 4;
    for (int kt = 0; kt < KT; kt++) {
        const int cur = kt & 1, nxt = cur ^ 1;
        CP_WAIT0();
        __syncthreads();
        if (kt + 1 < KT) {
            CP16(aD[nxt], aSrc + (kt + 1) * 16);
            CP16(b0D[nxt], bSrc0 + (kt + 1) * 16);
            CP16(b1D[nxt], bSrc1 + (kt + 1) * 16);
            CP_COMMIT();
        }
        unsigned afH[2][4], afL[2][4], bfH[4][2], bfL[4][2];
#pragma unroll
        for (int mt = 0; mt < 2; mt++) {
            int r = wm + mt * 16 + g;
            afH[mt][0] = AsH[cur][r][tig];     afH[mt][1] = AsH[cur][r + 8][tig];
            afH[mt][2] = AsH[cur][r][tig + 4]; afH[mt][3] = AsH[cur][r + 8][tig + 4];
            afL[mt][0] = AsL[cur][r][tig];     afL[mt][1] = AsL[cur][r + 8][tig];
            afL[mt][2] = AsL[cur][r][tig + 4]; afL[mt][3] = AsL[cur][r + 8][tig + 4];
        }
#pragma unroll
        for (int nt = 0; nt < 4; nt++) {
            int n = wn + nt * 8 + g;
            bfH[nt][0] = BsH[cur][n][tig]; bfH[nt][1] = BsH[cur][n][tig + 4];
            bfL[nt][0] = BsL[cur][n][tig]; bfL[nt][1] = BsL[cur][n][tig + 4];
        }
#pragma unroll
        for (int mt = 0; mt < 2; mt++)
#pragma unroll
            for (int nt = 0; nt < 4; nt++) {
                mma_bf16(acc[mt][nt], afL[mt], bfH[nt]);
                mma_bf16(acc[mt][nt], afH[mt], bfL[nt]);
                mma_bf16(acc[mt][nt], afH[mt], bfH[nt]);
            }
    }

#pragma unroll
    for (int mt = 0; mt < 2; mt++) {
#pragma unroll
        for (int nt = 0; nt < 4; nt++) {
            int r0 = bm + wm + mt * 16 + g, r1 = r0 + 8;
            int n0 = bn + wn + nt * 8 + 2 * tig;
            float2 v01 = make_float2(acc[mt][nt][0], acc[mt][nt][1]);
            float2 v23 = make_float2(acc[mt][nt][2], acc[mt][nt][3]);
            if (MODE == 0) {
                float2 x = *(const float2*)(bias1 + n0);
                float2 y = *(const float2*)(bias2 + n0);
                v01.x += x.x + y.x; v01.y += x.y + y.y;
                v23.x += x.x + y.x; v23.y += x.y + y.y;
            }
            if (MODE == 1) {
                float2 x = *(const float2*)(addM + (size_t)(r0 & 63) * GG + n0);
                float2 y = *(const float2*)(addM + (size_t)(r1 & 63) * GG + n0);
                v01.x += x.x; v01.y += x.y;
                v23.x += y.x; v23.y += y.y;
            }
            *(float2*)(C + (size_t)r0 * ldc + n0) = v01;
            *(float2*)(C + (size_t)r1 * ldc + n0) = v23;
        }
    }
}

// ---------------------------------------------------------------------------
// Recurrent step, 3-stage pipeline (proven), epilogue also emits int8 digits.
#define ST_W 2304

__global__ __launch_bounds__(256) void k_step(const bf* __restrict__ AH_,
                                              const bf* __restrict__ AL_, int t) {
    __shared__ unsigned sm[3 * ST_W];
    __shared__ float sg[64][33];
    const int tid = threadIdx.x;
    const int wid = tid >> 5, lane = tid & 31, g = lane >> 2, tig = lane & 3;
    const int wm = (wid & 1) * 32, wn = (wid >> 1) * 8;
    const int jj0 = blockIdx.x * 8;

    const bf* asrc;
    int acw;
    {
        int row = tid >> 2, sel = (tid >> 1) & 1, chunk = tid & 1;
        asrc = (sel ? AL_ : AH_) + (size_t)row * HH + chunk * 8;
        acw = sel * 768 + row * 12 + chunk * 4;
    }
    const bf* bsrc = nullptr;
    int bcw = 0;
    if (tid < 128) {
        int br = tid >> 2, bs = (tid >> 1) & 1, bc = tid & 1;
        int wrow = (br >> 3) * HH + jj0 + (br & 7);
        bsrc = (bs ? g_WhhL : g_WhhH) + (size_t)wrow * HH + bc * 8;
        bcw = 1536 + bs * 384 + br * 12 + bc * 4;
    }

    float acc[2][4] = {};
#pragma unroll
    for (int s = 0; s < 2; s++) {
        CP16(s2u(&sm[s * ST_W + acw]), asrc + s * 16);
        if (tid < 128) CP16(s2u(&sm[s * ST_W + bcw]), bsrc + s * 16);
        CP_COMMIT();
    }

    const int KT = HH >> 4;
    int buf = 0;
    for (int kt = 0; kt < KT; kt++) {
        CP_WAIT1();
        __syncthreads();
        if (kt + 2 < KT) {
            int s = (buf + 2) % 3;
            CP16(s2u(&sm[s * ST_W + acw]), asrc + (kt + 2) * 16);
            if (tid < 128) CP16(s2u(&sm[s * ST_W + bcw]), bsrc + (kt + 2) * 16);
            CP_COMMIT();
        } else {
            CP_COMMIT();
        }

        const unsigned* AHs = sm + buf * ST_W;
        const unsigned* ALs = AHs + 768;
        const unsigned* BHs = AHs + 1536;
        const unsigned* BLs = AHs + 1920;

        unsigned afH[2][4], afL[2][4], bfH[2], bfL[2];
#pragma unroll
        for (int mt = 0; mt < 2; mt++) {
            int r = (wm + mt * 16 + g) * 12;
            afH[mt][0] = AHs[r + tig];     afH[mt][1] = AHs[r + 96 + tig];
            afH[mt][2] = AHs[r + tig + 4]; afH[mt][3] = AHs[r + 96 + tig + 4];
            afL[mt][0] = ALs[r + tig];     afL[mt][1] = ALs[r + 96 + tig];
            afL[mt][2] = ALs[r + tig + 4]; afL[mt][3] = ALs[r + 96 + tig + 4];
        }
        int n = (wn + g) * 12;
        bfH[0] = BHs[n + tig]; bfH[1] = BHs[n + tig + 4];
        bfL[0] = BLs[n + tig]; bfL[1] = BLs[n + tig + 4];
#pragma unroll
        for (int mt = 0; mt < 2; mt++) {
            mma_bf16(acc[mt], afL[mt], bfH);
            mma_bf16(acc[mt], afH[mt], bfL);
            mma_bf16(acc[mt], afH[mt], bfH);
        }
        buf = (buf + 1) % 3;
    }

#pragma unroll
    for (int mt = 0; mt < 2; mt++)
#pragma unroll
        for (int q = 0; q < 4; q++) {
            int r = wm + mt * 16 + g + ((q >> 1) * 8);
            int j = wn + 2 * tig + (q & 1);
            sg[r][j] = acc[mt][q];
        }
    __syncthreads();

    const float* __restrict__ gx = g_gx + (size_t)t * 64 * GG;
    for (int u = tid; u < 512; u += 256) {
        int b = u >> 3, hh = u & 7;
        size_t gbase = (size_t)b * GG + jj0 + hh;
        float gi = sg[b][0 * 8 + hh] + gx[gbase];
        float gf = sg[b][1 * 8 + hh] + gx[gbase + HH];
        float gg = sg[b][2 * 8 + hh] + gx[gbase + 2 * HH];
        float go = sg[b][3 * 8 + hh] + gx[gbase + 3 * HH];
        int ci = b * HH + jj0 + hh;
        float cOld = g_c[ci];
        float si = 1.f / (1.f + expf(-gi));
        float sf = 1.f / (1.f + expf(-gf));
        float so = 1.f / (1.f + expf(-go));
        float cN = sf * cOld + si * tanhf(gg);
        float hN = so * tanhf(cN);
        g_c[ci] = cN;
        size_t hidx = ((size_t)t * 64 + b) * HH + jj0 + hh;
        bf hb = __float2bfloat16(hN);
        g_hsH[hidx] = hb;
        g_hsL[hidx] = __float2bfloat16(hN - __bfloat162float(hb));
        // int8 two-digit form for the logits IMMA (|h| < 1 guaranteed)
        int a1 = __float2int_rn(hN * 64.f);
        int a2 = __float2int_rn(fmaf(-128.f, (float)a1, hN * 8192.f));
        g_hsA1[hidx] = (s8)a1;
        g_hsA2[hidx] = (s8)a2;
    }
}

// ---------------------------------------------------------------------------
// IMMA logits GEMM: out[m,v] = (acc1*128 + accm) * M_v/2^19 + lin_b[v]
// BM=128, BN=64, k-slab=32 int8, 8 warps (4Mx2N), warp tile 32x32, 3-stage.
// Stage words: A1[128][12]@0 | A2@1536 | B1[64][12]@3072 | B2@3840  (4608 w)
#define IM_STG 4608
#define SMEM_IM (3 * IM_STG * 4)    // 54 KB

__global__ __launch_bounds__(256, 2) void k_logits_i8(const float* __restrict__ lin_b,
                                                      float* __restrict__ out) {
    extern __shared__ unsigned sm[];
    const int tid = threadIdx.x;
    const int wid = tid >> 5, lane = tid & 31, g = lane >> 2, tig = lane & 3;
    const int wm = (wid & 3) * 32, wn = (wid >> 2) * 32;
    const int bm = blockIdx.x * 128, bn = blockIdx.y * 64;

    // 768 16B copy tasks / 256 threads = 3 each
    const s8* csrc[3];
    int cword[3];
#pragma unroll
    for (int q = 0; q < 3; q++) {
        int i = tid + q * 256;
        if (i < 512) {
            int row = i >> 2, sel = (i >> 1) & 1, chunk = i & 1;
            csrc[q] = (sel ? g_hsA2 : g_hsA1) + (size_t)(bm + row) * HH + chunk * 16;
            cword[q] = sel * 1536 + row * 12 + chunk * 4;
        } else {
            int j = i - 512;
            int row = j >> 2, sel = (j >> 1) & 1, chunk = j & 1;
            csrc[q] = (sel ? g_linB2 : g_linB1) + (size_t)(bn + row) * HH + chunk * 16;
            cword[q] = 3072 + sel * 768 + row * 12 + chunk * 4;
        }
    }

    int acc1[2][4][4] = {};
    int accm[2][4][4] = {};

#pragma unroll
    for (int s = 0; s < 2; s++) {
#pragma unroll
        for (int q = 0; q < 3; q++)
            CP16(s2u(&sm[s * IM_STG + cword[q]]), csrc[q] + s * 32);
        CP_COMMIT();
    }

    const int KT = HH >> 5;   // 32 slabs of k=32
    int buf = 0;
    for (int kt = 0; kt < KT; kt++) {
        CP_WAIT1();
        __syncthreads();
        if (kt + 2 < KT) {
            int s = (buf + 2) % 3;
#pragma unroll
            for (int q = 0; q < 3; q++)
                CP16(s2u(&sm[s * IM_STG + cword[q]]), csrc[q] + (kt + 2) * 32);
            CP_COMMIT();
        } else {
            CP_COMMIT();
        }

        const unsigned* A1s = sm + buf * IM_STG;
        const unsigned* A2s = A1s + 1536;
        const unsigned* B1s = A1s + 3072;
        const unsigned* B2s = A1s + 3840;

        unsigned a1f[2][4], a2f[2][4];
#pragma unroll
        for (int mt = 0; mt < 2; mt++) {
            int r = (wm + mt * 16 + g) * 12;
            a1f[mt][0] = A1s[r + tig];     a1f[mt][1] = A1s[r + 96 + tig];
            a1f[mt][2] = A1s[r + tig + 4]; a1f[mt][3] = A1s[r + 96 + tig + 4];
            a2f[mt][0] = A2s[r + tig];     a2f[mt][1] = A2s[r + 96 + tig];
            a2f[mt][2] = A2s[r + tig + 4]; a2f[mt][3] = A2s[r + 96 + tig + 4];
        }
#pragma unroll
        for (int nt = 0; nt < 4; nt++) {
            int n = (wn + nt * 8 + g) * 12;
            unsigned b1[2], b2[2];
            b1[0] = B1s[n + tig]; b1[1] = B1s[n + tig + 4];
            b2[0] = B2s[n + tig]; b2[1] = B2s[n + tig + 4];
#pragma unroll
            for (int mt = 0; mt < 2; mt++) {
                mma_s8(acc1[mt][nt], a1f[mt], b1);
                mma_s8(accm[mt][nt], a1f[mt], b2);
                mma_s8(accm[mt][nt], a2f[mt], b1);
            }
        }
        buf = (buf + 1) % 3;
    }

#pragma unroll
    for (int mt = 0; mt < 2; mt++) {
#pragma unroll
        for (int q2 = 0; q2 < 2; q2++) {
            int m = bm + wm + mt * 16 + g + q2 * 8;
            if (m >= TT * BB) continue;
            float* orow = out + (size_t)m * VV + bn;
#pragma unroll
            for (int nt = 0; nt < 4; nt++) {
                int n0 = wn + nt * 8 + 2 * tig;
                float2 bb = *(const float2*)(lin_b + bn + n0);
                float2 sv = *(const float2*)(g_sv + bn + n0);
                float vx = fmaf((float)acc1[mt][nt][q2 * 2 + 0], 128.f,
                                (float)accm[mt][nt][q2 * 2 + 0]);
                float vy = fmaf((float)acc1[mt][nt][q2 * 2 + 1], 128.f,
                                (float)accm[mt][nt][q2 * 2 + 1]);
                float2 v = make_float2(fmaf(vx, sv.x * (1.f / 524288.f), bb.x),
                                       fmaf(vy, sv.y * (1.f / 524288.f), bb.y));
                *(float2*)(orow + n0) = v;
            }
        }
    }
}

// ---------------------------------------------------------------------------
extern "C" void kernel_launch(void* const* d_in, const int* in_sizes, int n_in,
                              void* d_out, int out_size) {
    const float* features = (const float*)d_in[0];
    const int*   captions = (const int*)d_in[1];
    const float* embed    = (const float*)d_in[3];
    const float* W_ih     = (const float*)d_in[4];
    const float* W_hh     = (const float*)d_in[5];
    const float* b_ih     = (const float*)d_in[6];
    const float* b_hh     = (const float*)d_in[7];
    const float* lin_W    = (const float*)d_in[10];
    const float* lin_b    = (const float*)d_in[11];
    float* out = (float*)d_out;

    bf *p_WihH, *p_WihL, *p_WhhH, *p_WhhL;
    bf *p_ctxH, *p_ctxL, *p_embH, *p_embL, *p_hsH, *p_hsL, *p_h0H, *p_h0L;
    s8 *p_linB1, *p_linB2;
    float *p_gbias, *p_gx;
    cudaGetSymbolAddress((void**)&p_WihH, g_WihH);
    cudaGetSymbolAddress((void**)&p_WihL, g_WihL);
    cudaGetSymbolAddress((void**)&p_WhhH, g_WhhH);
    cudaGetSymbolAddress((void**)&p_WhhL, g_WhhL);
    cudaGetSymbolAddress((void**)&p_ctxH, g_ctxH);
    cudaGetSymbolAddress((void**)&p_ctxL, g_ctxL);
    cudaGetSymbolAddress((void**)&p_embH, g_embH);
    cudaGetSymbolAddress((void**)&p_embL, g_embL);
    cudaGetSymbolAddress((void**)&p_hsH, g_hsH);
    cudaGetSymbolAddress((void**)&p_hsL, g_hsL);
    cudaGetSymbolAddress((void**)&p_h0H, g_h0H);
    cudaGetSymbolAddress((void**)&p_h0L, g_h0L);
    cudaGetSymbolAddress((void**)&p_linB1, g_linB1);
    cudaGetSymbolAddress((void**)&p_linB2, g_linB2);
    cudaGetSymbolAddress((void**)&p_gbias, g_gbias);
    cudaGetSymbolAddress((void**)&p_gx, g_gx);

    cudaFuncSetAttribute(k_logits_i8, cudaFuncAttributeMaxDynamicSharedMemorySize, SMEM_IM);

    k_init<<<(BB * HH + 255) / 256, 256>>>();
    int n4;
    // lin_W: per-row scale + int8 two-digit quantization
    k_rowmax<<<VV / 8, 256>>>(lin_W);
    n4 = VV * HH / 4;
    k_qw<<<(n4 / 2 + 255) / 256, 256>>>((const float4*)lin_W, (unsigned*)p_linB1,
                                        (unsigned*)p_linB2, n4);
    n4 = GG * 1536 / 4;
    k_conv<<<(n4 / 2 + 255) / 256, 256>>>((const float4*)W_ih, (uint2*)p_WihH, (uint2*)p_WihL, n4);
    n4 = GG * HH / 4;
    k_conv<<<(n4 / 2 + 255) / 256, 256>>>((const float4*)W_hh, (uint2*)p_WhhH, (uint2*)p_WhhL, n4);
    k_ctx<<<BB, 256>>>(features);
    k_emb<<<(TT * BB * EE / 4 + 255) / 256, 256>>>(embed, captions);
    k_mm<0><<<dim3(GG / 128, 1), 256>>>(p_ctxH, p_ctxL, HH,
                                        p_WihH + 512, p_WihL + 512, 1536,
                                        p_gbias, GG, HH, b_ih, b_hh, nullptr);
    k_mm<1><<<dim3(GG / 128, TT), 256>>>(p_embH, p_embL, EE,
                                         p_WihH, p_WihL, 1536,
                                         p_gx, GG, EE, nullptr, nullptr, p_gbias);
    for (int t = 0; t < TT; t++) {
        const bf* AH = t ? p_hsH + (size_t)(t - 1) * BB * HH : p_h0H;
        const bf* AL = t ? p_hsL + (size_t)(t - 1) * BB * HH : p_h0L;
        k_step<<<128, 256>>>(AH, AL, t);
    }
    // logits via int8 IMMA (M-fast grid: B tiles shared in L2; B planes fit L2 entirely)
    k_logits_i8<<<dim3(MPAD / 128, VV / 64), 256, SMEM_IM>>>(lin_b, out);
}

// round 12
// speedup vs baseline: 1.2419x; 1.2419x over previous
#include <cuda_runtime.h>
#include <cuda_bf16.h>
#include <math.h>
#include <stdint.h>

#define BB 64
#define TT 31
#define EE 512
#define HH 1024
#define GG 4096
#define VV 32000
#define MPAD 2048
#define NCONV 529           // lin_W conv blocks folded into each of 31 step launches
typedef __nv_bfloat16 bf;

__device__ __align__(16) bf g_linWH[(size_t)VV * HH], g_linWL[(size_t)VV * HH];
__device__ __align__(16) bf g_WihH[(size_t)GG * 1536], g_WihL[(size_t)GG * 1536];
__device__ __align__(16) bf g_WhhH[(size_t)GG * HH], g_WhhL[(size_t)GG * HH];
__device__ __align__(16) bf g_ctxH[BB * HH], g_ctxL[BB * HH];
__device__ __align__(16) bf g_embH[(size_t)TT * BB * EE], g_embL[(size_t)TT * BB * EE];
__device__ __align__(16) bf g_hsH[(size_t)MPAD * HH], g_hsL[(size_t)MPAD * HH];
__device__ __align__(16) bf g_h0H[BB * HH], g_h0L[BB * HH];
__device__ float g_gbias[BB * GG];
__device__ float g_gx[(size_t)TT * BB * GG];
__device__ float g_c[BB * HH];

// ---------------------------------------------------------------------------
#define CP16(dst, src) asm volatile("cp.async.ca.shared.global [%0], [%1], 16;" :: "r"(dst), "l"(src) : "memory")
#define CP_COMMIT() asm volatile("cp.async.commit_group;" ::: "memory")
#define CP_WAIT0() asm volatile("cp.async.wait_group 0;" ::: "memory")
#define CP_WAIT1() asm volatile("cp.async.wait_group 1;" ::: "memory")

__device__ __forceinline__ unsigned s2u(const void* p) {
    return (unsigned)__cvta_generic_to_shared(p);
}
__device__ __forceinline__ void mma_bf16(float c[4], const unsigned a[4], const unsigned b[2]) {
    asm("mma.sync.aligned.m16n8k16.row.col.f32.bf16.bf16.f32 "
        "{%0,%1,%2,%3},{%4,%5,%6,%7},{%8,%9},{%0,%1,%2,%3};"
        : "+f"(c[0]), "+f"(c[1]), "+f"(c[2]), "+f"(c[3])
        : "r"(a[0]), "r"(a[1]), "r"(a[2]), "r"(a[3]), "r"(b[0]), "r"(b[1]));
}
__device__ __forceinline__ void split2(float x, float y, unsigned& hi, unsigned& lo) {
    bf hx = __float2bfloat16(x), hy = __float2bfloat16(y);
    __nv_bfloat162 H = __halves2bfloat162(hx, hy);
    __nv_bfloat162 L = __halves2bfloat162(__float2bfloat16(x - __bfloat162float(hx)),
                                          __float2bfloat16(y - __bfloat162float(hy)));
    hi = *(unsigned*)&H;
    lo = *(unsigned*)&L;
}

// ---------------------------------------------------------------------------
__global__ void k_init() {
    int i = blockIdx.x * blockDim.x + threadIdx.x;
    if (i < BB * HH) {
        g_h0H[i] = __float2bfloat16(0.f);
        g_h0L[i] = __float2bfloat16(0.f);
        g_c[i] = 0.f;
    }
    if (i < (MPAD - TT * BB) * HH) {
        size_t p = (size_t)TT * BB * HH + i;
        g_hsH[p] = __float2bfloat16(0.f);
        g_hsL[p] = __float2bfloat16(0.f);
    }
}

// fp32 -> bf16 hi/lo; 2 independent float4 per thread (MLP=2)
__global__ void k_conv(const float4* __restrict__ S, uint2* __restrict__ H,
                       uint2* __restrict__ L, int n4) {
    int i = blockIdx.x * blockDim.x + threadIdx.x;
    int half = n4 >> 1;
    if (i >= half) return;
    float4 v0 = S[i];
    float4 v1 = S[i + half];
    uint2 h0, l0, h1, l1;
    split2(v0.x, v0.y, h0.x, l0.x);
    split2(v0.z, v0.w, h0.y, l0.y);
    split2(v1.x, v1.y, h1.x, l1.x);
    split2(v1.z, v1.w, h1.y, l1.y);
    H[i] = h0; L[i] = l0;
    H[i + half] = h1; L[i + half] = l1;
}

__global__ void k_ctx(const float* __restrict__ features) {
    int b = blockIdx.x;
    for (int h = threadIdx.x; h < HH; h += blockDim.x) {
        const float* p = features + (size_t)b * 64 * HH + h;
        float s = 0.f;
#pragma unroll 8
        for (int l = 0; l < 64; l++) s += p[(size_t)l * HH];
        bf hi = __float2bfloat16(s);
        g_ctxH[b * HH + h] = hi;
        g_ctxL[b * HH + h] = __float2bfloat16(s - __bfloat162float(hi));
    }
}

__global__ void k_emb(const float* __restrict__ embed, const int* __restrict__ captions) {
    int v = blockIdx.x * blockDim.x + threadIdx.x;
    int m = v >> 7;
    int e4 = (v & 127) << 2;
    int t = m / 64, b = m % 64;
    int cap = captions[b * 32 + t];
    float4 val = *(const float4*)(embed + (size_t)cap * EE + e4);
    uint2 h, l;
    split2(val.x, val.y, h.x, l.x);
    split2(val.z, val.w, h.y, l.y);
    ((uint2*)g_embH)[((size_t)m * EE + e4) >> 2] = h;
    ((uint2*)g_embL)[((size_t)m * EE + e4) >> 2] = l;
}

// ---------------------------------------------------------------------------
// mma.sync bf16x3 GEMM for gbias (BM=64, BN=128, 2-stage). Proven config.
__global__ __launch_bounds__(256) void k_mm0(
    const bf* __restrict__ AH, const bf* __restrict__ AL, int lda,
    const bf* __restrict__ BH, const bf* __restrict__ BL, int ldb,
    float* __restrict__ C, int ldc, int K,
    const float* __restrict__ bias1, const float* __restrict__ bias2)
{
    __shared__ unsigned AsH[2][64][12], AsL[2][64][12];
    __shared__ unsigned BsH[2][128][12], BsL[2][128][12];
    const int tid = threadIdx.x;
    const int wid = tid >> 5, lane = tid & 31, g = lane >> 2, tig = lane & 3;
    const int wm = (wid & 1) * 32, wn = (wid >> 1) * 32;
    const int bm = blockIdx.y * 64, bn = blockIdx.x * 128;

    const int arow = tid >> 2, asel = (tid >> 1) & 1, achk = tid & 1;
    const bf* aSrc = (asel ? AL : AH) + (size_t)(bm + arow) * lda + achk * 8;
    unsigned aD[2] = { s2u(&(asel ? AsL : AsH)[0][arow][achk * 4]),
                       s2u(&(asel ? AsL : AsH)[1][arow][achk * 4]) };
    const int b0r = tid >> 2, b0s = (tid >> 1) & 1, b0c = tid & 1;
    const int id1 = tid + 256;
    const int b1r = id1 >> 2, b1s = (id1 >> 1) & 1, b1c = id1 & 1;
    const bf* bSrc0 = (b0s ? BL : BH) + (size_t)(bn + b0r) * ldb + b0c * 8;
    const bf* bSrc1 = (b1s ? BL : BH) + (size_t)(bn + b1r) * ldb + b1c * 8;
    unsigned b0D[2] = { s2u(&(b0s ? BsL : BsH)[0][b0r][b0c * 4]),
                        s2u(&(b0s ? BsL : BsH)[1][b0r][b0c * 4]) };
    unsigned b1D[2] = { s2u(&(b1s ? BsL : BsH)[0][b1r][b1c * 4]),
                        s2u(&(b1s ? BsL : BsH)[1][b1r][b1c * 4]) };

    float acc[2][4][4] = {};
    CP16(aD[0], aSrc); CP16(b0D[0], bSrc0); CP16(b1D[0], bSrc1); CP_COMMIT();

    const int KT = K >> 4;
    for (int kt = 0; kt < KT; kt++) {
        const int cur = kt & 1, nxt = cur ^ 1;
        CP_WAIT0();
        __syncthreads();
        if (kt + 1 < KT) {
            CP16(aD[nxt], aSrc + (kt + 1) * 16);
            CP16(b0D[nxt], bSrc0 + (kt + 1) * 16);
            CP16(b1D[nxt], bSrc1 + (kt + 1) * 16);
            CP_COMMIT();
        }
        unsigned afH[2][4], afL[2][4], bfH[4][2], bfL[4][2];
#pragma unroll
        for (int mt = 0; mt < 2; mt++) {
            int r = wm + mt * 16 + g;
            afH[mt][0] = AsH[cur][r][tig];     afH[mt][1] = AsH[cur][r + 8][tig];
            afH[mt][2] = AsH[cur][r][tig + 4]; afH[mt][3] = AsH[cur][r + 8][tig + 4];
            afL[mt][0] = AsL[cur][r][tig];     afL[mt][1] = AsL[cur][r + 8][tig];
            afL[mt][2] = AsL[cur][r][tig + 4]; afL[mt][3] = AsL[cur][r + 8][tig + 4];
        }
#pragma unroll
        for (int nt = 0; nt < 4; nt++) {
            int n = wn + nt * 8 + g;
            bfH[nt][0] = BsH[cur][n][tig]; bfH[nt][1] = BsH[cur][n][tig + 4];
            bfL[nt][0] = BsL[cur][n][tig]; bfL[nt][1] = BsL[cur][n][tig + 4];
        }
#pragma unroll
        for (int mt = 0; mt < 2; mt++)
#pragma unroll
            for (int nt = 0; nt < 4; nt++) {
                mma_bf16(acc[mt][nt], afL[mt], bfH[nt]);
                mma_bf16(acc[mt][nt], afH[mt], bfL[nt]);
                mma_bf16(acc[mt][nt], afH[mt], bfH[nt]);
            }
    }

#pragma unroll
    for (int mt = 0; mt < 2; mt++) {
#pragma unroll
        for (int nt = 0; nt < 4; nt++) {
            int r0 = bm + wm + mt * 16 + g, r1 = r0 + 8;
            int n0 = bn + wn + nt * 8 + 2 * tig;
            float2 x = *(const float2*)(bias1 + n0);
            float2 y = *(const float2*)(bias2 + n0);
            float2 v01 = make_float2(acc[mt][nt][0] + x.x + y.x, acc[mt][nt][1] + x.y + y.y);
            float2 v23 = make_float2(acc[mt][nt][2] + x.x + y.x, acc[mt][nt][3] + x.y + y.y);
            *(float2*)(C + (size_t)r0 * ldc + n0) = v01;
            *(float2*)(C + (size_t)r1 * ldc + n0) = v23;
        }
    }
}

// ---------------------------------------------------------------------------
// gx GEMM, 3-stage pipeline: gx[(t*64+b),n] = emb[t] @ W_ih[:, :512]^T + gbias[b,n]
// BM=64 (one t), BN=128, K=512. Stage: AH[64][12]@0 | AL@768 | BH[128][12]@1536 | BL@3072
#define GX_STG 4608

__global__ __launch_bounds__(256) void k_gx3() {
    __shared__ unsigned sm[3 * GX_STG];
    const int tid = threadIdx.x;
    const int wid = tid >> 5, lane = tid & 31, g = lane >> 2, tig = lane & 3;
    const int wm = (wid & 1) * 32, wn = (wid >> 1) * 32;
    const int t = blockIdx.y, bm = t * 64, bn = blockIdx.x * 128;

    // copy tasks: A 256 (1/thread), B 512 (2/thread) = 3 total
    const bf* csrc[3];
    int cword[3];
    {
        int row = tid >> 2, sel = (tid >> 1) & 1, chunk = tid & 1;
        csrc[0] = (sel ? g_embL : g_embH) + (size_t)(bm + row) * EE + chunk * 8;
        cword[0] = sel * 768 + row * 12 + chunk * 4;
    }
#pragma unroll
    for (int q = 1; q < 3; q++) {
        int j = tid + (q - 1) * 256;
        int row = j >> 2, sel = (j >> 1) & 1, chunk = j & 1;
        csrc[q] = (sel ? g_WihL : g_WihH) + (size_t)(bn + row) * 1536 + chunk * 8;
        cword[q] = 1536 + sel * 1536 + row * 12 + chunk * 4;
    }

    float acc[2][4][4] = {};
#pragma unroll
    for (int s = 0; s < 2; s++) {
#pragma unroll
        for (int q = 0; q < 3; q++)
            CP16(s2u(&sm[s * GX_STG + cword[q]]), csrc[q] + s * 16);
        CP_COMMIT();
    }

    const int KT = EE >> 4;   // 32
    int buf = 0;
    for (int kt = 0; kt < KT; kt++) {
        CP_WAIT1();
        __syncthreads();
        if (kt + 2 < KT) {
            int s = (buf + 2) % 3;
#pragma unroll
            for (int q = 0; q < 3; q++)
                CP16(s2u(&sm[s * GX_STG + cword[q]]), csrc[q] + (kt + 2) * 16);
            CP_COMMIT();
        } else {
            CP_COMMIT();
        }

        const unsigned* AHs = sm + buf * GX_STG;
        const unsigned* ALs = AHs + 768;
        const unsigned* BHs = AHs + 1536;
        const unsigned* BLs = AHs + 3072;

        unsigned afH[2][4], afL[2][4];
#pragma unroll
        for (int mt = 0; mt < 2; mt++) {
            int r = (wm + mt * 16 + g) * 12;
            afH[mt][0] = AHs[r + tig];     afH[mt][1] = AHs[r + 96 + tig];
            afH[mt][2] = AHs[r + tig + 4]; afH[mt][3] = AHs[r + 96 + tig + 4];
            afL[mt][0] = ALs[r + tig];     afL[mt][1] = ALs[r + 96 + tig];
            afL[mt][2] = ALs[r + tig + 4]; afL[mt][3] = ALs[r + 96 + tig + 4];
        }
#pragma unroll
        for (int nt = 0; nt < 4; nt++) {
            int n = (wn + nt * 8 + g) * 12;
            unsigned bH[2], bL[2];
            bH[0] = BHs[n + tig]; bH[1] = BHs[n + tig + 4];
            bL[0] = BLs[n + tig]; bL[1] = BLs[n + tig + 4];
#pragma unroll
            for (int mt = 0; mt < 2; mt++) {
                mma_bf16(acc[mt][nt], afL[mt], bH);
                mma_bf16(acc[mt][nt], afH[mt], bL);
                mma_bf16(acc[mt][nt], afH[mt], bH);
            }
        }
        buf = (buf + 1) % 3;
    }

    float* __restrict__ C = g_gx;
#pragma unroll
    for (int mt = 0; mt < 2; mt++) {
#pragma unroll
        for (int nt = 0; nt < 4; nt++) {
            int r0 = bm + wm + mt * 16 + g, r1 = r0 + 8;
            int n0 = bn + wn + nt * 8 + 2 * tig;
            float2 x = *(const float2*)(g_gbias + (size_t)(r0 & 63) * GG + n0);
            float2 y = *(const float2*)(g_gbias + (size_t)(r1 & 63) * GG + n0);
            float2 v01 = make_float2(acc[mt][nt][0] + x.x, acc[mt][nt][1] + x.y);
            float2 v23 = make_float2(acc[mt][nt][2] + y.x, acc[mt][nt][3] + y.y);
            *(float2*)(C + (size_t)r0 * GG + n0) = v01;
            *(float2*)(C + (size_t)r1 * GG + n0) = v23;
        }
    }
}

// ---------------------------------------------------------------------------
// Recurrent step, 3-stage pipeline + folded lin_W conversion blocks.
// Blocks [0,128): GEMM+LSTM. Blocks [128,128+NCONV): convert a chunk of lin_W.
#define ST_W 2304

__global__ __launch_bounds__(256) void k_step(const bf* __restrict__ AH_,
                                              const bf* __restrict__ AL_, int t,
                                              const float4* __restrict__ linW) {
    __shared__ unsigned sm[3 * ST_W];
    __shared__ float sg[64][33];
    const int tid = threadIdx.x;

    if (blockIdx.x >= 128) {
        // lin_W fp32 -> bf16 hi/lo chunk (runs in the step's memory shadow)
        int chunk = t * NCONV + (int)blockIdx.x - 128;
        int i = chunk * 256 + tid;
        const int half = VV * HH / 8;          // float4-pair tasks
        if (i < half) {
            float4 v0 = linW[i];
            float4 v1 = linW[i + half];
            uint2 h0, l0, h1, l1;
            split2(v0.x, v0.y, h0.x, l0.x);
            split2(v0.z, v0.w, h0.y, l0.y);
            split2(v1.x, v1.y, h1.x, l1.x);
            split2(v1.z, v1.w, h1.y, l1.y);
            ((uint2*)g_linWH)[i] = h0; ((uint2*)g_linWL)[i] = l0;
            ((uint2*)g_linWH)[i + half] = h1; ((uint2*)g_linWL)[i + half] = l1;
        }
        return;
    }

    const int wid = tid >> 5, lane = tid & 31, g = lane >> 2, tig = lane & 3;
    const int wm = (wid & 1) * 32, wn = (wid >> 1) * 8;
    const int jj0 = blockIdx.x * 8;

    const bf* asrc;
    int acw;
    {
        int row = tid >> 2, sel = (tid >> 1) & 1, chunk = tid & 1;
        asrc = (sel ? AL_ : AH_) + (size_t)row * HH + chunk * 8;
        acw = sel * 768 + row * 12 + chunk * 4;
    }
    const bf* bsrc = nullptr;
    int bcw = 0;
    if (tid < 128) {
        int br = tid >> 2, bs = (tid >> 1) & 1, bc = tid & 1;
        int wrow = (br >> 3) * HH + jj0 + (br & 7);
        bsrc = (bs ? g_WhhL : g_WhhH) + (size_t)wrow * HH + bc * 8;
        bcw = 1536 + bs * 384 + br * 12 + bc * 4;
    }

    float acc[2][4] = {};
#pragma unroll
    for (int s = 0; s < 2; s++) {
        CP16(s2u(&sm[s * ST_W + acw]), asrc + s * 16);
        if (tid < 128) CP16(s2u(&sm[s * ST_W + bcw]), bsrc + s * 16);
        CP_COMMIT();
    }

    const int KT = HH >> 4;
    int buf = 0;
    for (int kt = 0; kt < KT; kt++) {
        CP_WAIT1();
        __syncthreads();
        if (kt + 2 < KT) {
            int s = (buf + 2) % 3;
            CP16(s2u(&sm[s * ST_W + acw]), asrc + (kt + 2) * 16);
            if (tid < 128) CP16(s2u(&sm[s * ST_W + bcw]), bsrc + (kt + 2) * 16);
            CP_COMMIT();
        } else {
            CP_COMMIT();
        }

        const unsigned* AHs = sm + buf * ST_W;
        const unsigned* ALs = AHs + 768;
        const unsigned* BHs = AHs + 1536;
        const unsigned* BLs = AHs + 1920;

        unsigned afH[2][4], afL[2][4], bfH[2], bfL[2];
#pragma unroll
        for (int mt = 0; mt < 2; mt++) {
            int r = (wm + mt * 16 + g) * 12;
            afH[mt][0] = AHs[r + tig];     afH[mt][1] = AHs[r + 96 + tig];
            afH[mt][2] = AHs[r + tig + 4]; afH[mt][3] = AHs[r + 96 + tig + 4];
            afL[mt][0] = ALs[r + tig];     afL[mt][1] = ALs[r + 96 + tig];
            afL[mt][2] = ALs[r + tig + 4]; afL[mt][3] = ALs[r + 96 + tig + 4];
        }
        int n = (wn + g) * 12;
        bfH[0] = BHs[n + tig]; bfH[1] = BHs[n + tig + 4];
        bfL[0] = BLs[n + tig]; bfL[1] = BLs[n + tig + 4];
#pragma unroll
        for (int mt = 0; mt < 2; mt++) {
            mma_bf16(acc[mt], afL[mt], bfH);
            mma_bf16(acc[mt], afH[mt], bfL);
            mma_bf16(acc[mt], afH[mt], bfH);
        }
        buf = (buf + 1) % 3;
    }

#pragma unroll
    for (int mt = 0; mt < 2; mt++)
#pragma unroll
        for (int q = 0; q < 4; q++) {
            int r = wm + mt * 16 + g + ((q >> 1) * 8);
            int j = wn + 2 * tig + (q & 1);
            sg[r][j] = acc[mt][q];
        }
    __syncthreads();

    const float* __restrict__ gx = g_gx + (size_t)t * 64 * GG;
    for (int u = tid; u < 512; u += 256) {
        int b = u >> 3, hh = u & 7;
        size_t gbase = (size_t)b * GG + jj0 + hh;
        float gi = sg[b][0 * 8 + hh] + gx[gbase];
        float gf = sg[b][1 * 8 + hh] + gx[gbase + HH];
        float gg = sg[b][2 * 8 + hh] + gx[gbase + 2 * HH];
        float go = sg[b][3 * 8 + hh] + gx[gbase + 3 * HH];
        int ci = b * HH + jj0 + hh;
        float cOld = g_c[ci];
        float si = 1.f / (1.f + expf(-gi));
        float sf = 1.f / (1.f + expf(-gf));
        float so = 1.f / (1.f + expf(-go));
        float cN = sf * cOld + si * tanhf(gg);
        float hN = so * tanhf(cN);
        g_c[ci] = cN;
        size_t hidx = ((size_t)t * 64 + b) * HH + jj0 + hh;
        bf hb = __float2bfloat16(hN);
        g_hsH[hidx] = hb;
        g_hsL[hidx] = __float2bfloat16(hN - __bfloat162float(hb));
    }
}

// ---------------------------------------------------------------------------
// Logits GEMM: BM=128, BN=128, BK=16, 8 warps (4Mx2N), warp 32x64, 3-stage.
#define LG_STG 6144
#define SMEM_LG3 (3 * LG_STG * 4)    // 72 KB

__global__ __launch_bounds__(256, 2) void k_logits3(const float* __restrict__ lin_b,
                                                    float* __restrict__ out) {
    extern __shared__ unsigned sm[];
    const int tid = threadIdx.x;
    const int wid = tid >> 5, lane = tid & 31, g = lane >> 2, tig = lane & 3;
    const int wm = (wid & 3) * 32, wn = (wid >> 2) * 64;
    const int bm = blockIdx.x * 128, bn = blockIdx.y * 128;

    const bf* csrc[4];
    int cword[4];
#pragma unroll
    for (int q = 0; q < 4; q++) {
        int i = tid + q * 256;
        int row = (i >> 2) & 127, sel = (i >> 1) & 1, chunk = i & 1;
        if (i < 512) {
            csrc[q] = (sel ? g_hsL : g_hsH) + (size_t)(bm + row) * HH + chunk * 8;
            cword[q] = sel * 1536 + row * 12 + chunk * 4;
        } else {
            csrc[q] = (sel ? g_linWL : g_linWH) + (size_t)(bn + row) * HH + chunk * 8;
            cword[q] = 3072 + sel * 1536 + row * 12 + chunk * 4;
        }
    }

    float acc[2][8][4] = {};

#pragma unroll
    for (int s = 0; s < 2; s++) {
#pragma unroll
        for (int q = 0; q < 4; q++)
            CP16(s2u(&sm[s * LG_STG + cword[q]]), csrc[q] + s * 16);
        CP_COMMIT();
    }

    const int KT = HH >> 4;
    int buf = 0;
    for (int kt = 0; kt < KT; kt++) {
        CP_WAIT1();
        __syncthreads();
        if (kt + 2 < KT) {
            int s = (buf + 2) % 3;
#pragma unroll
            for (int q = 0; q < 4; q++)
                CP16(s2u(&sm[s * LG_STG + cword[q]]), csrc[q] + (kt + 2) * 16);
            CP_COMMIT();
        } else {
            CP_COMMIT();
        }

        const unsigned* AHs = sm + buf * LG_STG;
        const unsigned* ALs = AHs + 1536;
        const unsigned* BHs = AHs + 3072;
        const unsigned* BLs = AHs + 4608;

        unsigned aH[2][4], aL[2][4];
#pragma unroll
        for (int mt = 0; mt < 2; mt++) {
            int r = (wm + mt * 16 + g) * 12;
            aH[mt][0] = AHs[r + tig];     aH[mt][1] = AHs[r + 96 + tig];
            aH[mt][2] = AHs[r + tig + 4]; aH[mt][3] = AHs[r + 96 + tig + 4];
            aL[mt][0] = ALs[r + tig];     aL[mt][1] = ALs[r + 96 + tig];
            aL[mt][2] = ALs[r + tig + 4]; aL[mt][3] = ALs[r + 96 + tig + 4];
        }
#pragma unroll
        for (int nt = 0; nt < 8; nt++) {
            int n = (wn + nt * 8 + g) * 12;
            unsigned bH[2], bL[2];
            bH[0] = BHs[n + tig]; bH[1] = BHs[n + tig + 4];
            bL[0] = BLs[n + tig]; bL[1] = BLs[n + tig + 4];
#pragma unroll
            for (int mt = 0; mt < 2; mt++) {
                mma_bf16(acc[mt][nt], aL[mt], bH);
                mma_bf16(acc[mt][nt], aH[mt], bL);
                mma_bf16(acc[mt][nt], aH[mt], bH);
            }
        }
        buf = (buf + 1) % 3;
    }

#pragma unroll
    for (int mt = 0; mt < 2; mt++) {
#pragma unroll
        for (int q2 = 0; q2 < 2; q2++) {
            int m = bm + wm + mt * 16 + g + q2 * 8;
            if (m >= TT * BB) continue;
            float* orow = out + (size_t)m * VV + bn;
#pragma unroll
            for (int nt = 0; nt < 8; nt++) {
                int n0 = wn + nt * 8 + 2 * tig;
                float2 bb = *(const float2*)(lin_b + bn + n0);
                float2 v = make_float2(acc[mt][nt][q2 * 2] + bb.x,
                                       acc[mt][nt][q2 * 2 + 1] + bb.y);
                *(float2*)(orow + n0) = v;
            }
        }
    }
}

// ---------------------------------------------------------------------------
extern "C" void kernel_launch(void* const* d_in, const int* in_sizes, int n_in,
                              void* d_out, int out_size) {
    const float* features = (const float*)d_in[0];
    const int*   captions = (const int*)d_in[1];
    const float* embed    = (const float*)d_in[3];
    const float* W_ih     = (const float*)d_in[4];
    const float* W_hh     = (const float*)d_in[5];
    const float* b_ih     = (const float*)d_in[6];
    const float* b_hh     = (const float*)d_in[7];
    const float* lin_W    = (const float*)d_in[10];
    const float* lin_b    = (const float*)d_in[11];
    float* out = (float*)d_out;

    bf *p_WihH, *p_WihL, *p_WhhH, *p_WhhL;
    bf *p_ctxH, *p_ctxL, *p_hsH, *p_hsL, *p_h0H, *p_h0L;
    float *p_gbias;
    cudaGetSymbolAddress((void**)&p_WihH, g_WihH);
    cudaGetSymbolAddress((void**)&p_WihL, g_WihL);
    cudaGetSymbolAddress((void**)&p_WhhH, g_WhhH);
    cudaGetSymbolAddress((void**)&p_WhhL, g_WhhL);
    cudaGetSymbolAddress((void**)&p_ctxH, g_ctxH);
    cudaGetSymbolAddress((void**)&p_ctxL, g_ctxL);
    cudaGetSymbolAddress((void**)&p_hsH, g_hsH);
    cudaGetSymbolAddress((void**)&p_hsL, g_hsL);
    cudaGetSymbolAddress((void**)&p_h0H, g_h0H);
    cudaGetSymbolAddress((void**)&p_h0L, g_h0L);
    cudaGetSymbolAddress((void**)&p_gbias, g_gbias);

    cudaFuncSetAttribute(k_logits3, cudaFuncAttributeMaxDynamicSharedMemorySize, SMEM_LG3);

    k_init<<<(BB * HH + 255) / 256, 256>>>();
    int n4;
    n4 = GG * 1536 / 4;
    k_conv<<<(n4 / 2 + 255) / 256, 256>>>((const float4*)W_ih, (uint2*)p_WihH, (uint2*)p_WihL, n4);
    n4 = GG * HH / 4;
    k_conv<<<(n4 / 2 + 255) / 256, 256>>>((const float4*)W_hh, (uint2*)p_WhhH, (uint2*)p_WhhL, n4);
    k_ctx<<<BB, 256>>>(features);
    k_emb<<<(TT * BB * EE / 4 + 255) / 256, 256>>>(embed, captions);
    // gbias = ctx @ W_ih[:,512:]^T + b_ih + b_hh
    k_mm0<<<dim3(GG / 128, 1), 256>>>(p_ctxH, p_ctxL, HH,
                                      p_WihH + 512, p_WihL + 512, 1536,
                                      p_gbias, GG, HH, b_ih, b_hh);
    // gx = emb @ W_ih[:,:512]^T + gbias   (3-stage pipeline)
    k_gx3<<<dim3(GG / 128, TT), 256>>>();
    // 31 recurrent steps; each launch also converts 1/31 of lin_W in its shadow
    for (int t = 0; t < TT; t++) {
        const bf* AH = t ? p_hsH + (size_t)(t - 1) * BB * HH : p_h0H;
        const bf* AL = t ? p_hsL + (size_t)(t - 1) * BB * HH : p_h0L;
        k_step<<<128 + NCONV, 256>>>(AH, AL, t, (const float4*)lin_W);
    }
    // logits = hs @ lin_W^T + lin_b
    k_logits3<<<dim3(MPAD / 128, VV / 128), 256, SMEM_LG3>>>(lin_b, out);
}

// round 13
// speedup vs baseline: 1.4656x; 1.1801x over previous
#include <cuda_runtime.h>
#include <cuda_bf16.h>
#include <math.h>
#include <stdint.h>

#define BB 64
#define TT 31
#define EE 512
#define HH 1024
#define GG 4096
#define VV 32000
#define MPAD 2048
typedef __nv_bfloat16 bf;

__device__ __align__(16) bf g_linWH[(size_t)VV * HH], g_linWL[(size_t)VV * HH];
__device__ __align__(16) bf g_WihH[(size_t)GG * 1536], g_WihL[(size_t)GG * 1536];
__device__ __align__(16) bf g_WhhH[(size_t)GG * HH], g_WhhL[(size_t)GG * HH];
__device__ __align__(16) bf g_ctxH[BB * HH], g_ctxL[BB * HH];
__device__ __align__(16) bf g_embH[(size_t)TT * BB * EE], g_embL[(size_t)TT * BB * EE];
__device__ __align__(16) bf g_hsH[(size_t)MPAD * HH], g_hsL[(size_t)MPAD * HH];
__device__ __align__(16) bf g_h0H[BB * HH], g_h0L[BB * HH];
__device__ float g_gbias[BB * GG];
__device__ float g_gx[(size_t)TT * BB * GG];
__device__ float g_c[BB * HH];

// ---------------------------------------------------------------------------
#define CP16(dst, src) asm volatile("cp.async.ca.shared.global [%0], [%1], 16;" :: "r"(dst), "l"(src) : "memory")
#define CP_COMMIT() asm volatile("cp.async.commit_group;" ::: "memory")
#define CP_WAIT0() asm volatile("cp.async.wait_group 0;" ::: "memory")
#define CP_WAIT1() asm volatile("cp.async.wait_group 1;" ::: "memory")

__device__ __forceinline__ unsigned s2u(const void* p) {
    return (unsigned)__cvta_generic_to_shared(p);
}
__device__ __forceinline__ void mma_bf16(float c[4], const unsigned a[4], const unsigned b[2]) {
    asm("mma.sync.aligned.m16n8k16.row.col.f32.bf16.bf16.f32 "
        "{%0,%1,%2,%3},{%4,%5,%6,%7},{%8,%9},{%0,%1,%2,%3};"
        : "+f"(c[0]), "+f"(c[1]), "+f"(c[2]), "+f"(c[3])
        : "r"(a[0]), "r"(a[1]), "r"(a[2]), "r"(a[3]), "r"(b[0]), "r"(b[1]));
}
__device__ __forceinline__ void split2(float x, float y, unsigned& hi, unsigned& lo) {
    bf hx = __float2bfloat16(x), hy = __float2bfloat16(y);
    __nv_bfloat162 H = __halves2bfloat162(hx, hy);
    __nv_bfloat162 L = __halves2bfloat162(__float2bfloat16(x - __bfloat162float(hx)),
                                          __float2bfloat16(y - __bfloat162float(hy)));
    hi = *(unsigned*)&H;
    lo = *(unsigned*)&L;
}

// ---------------------------------------------------------------------------
__global__ void k_init() {
    int i = blockIdx.x * blockDim.x + threadIdx.x;
    if (i < BB * HH) {
        g_h0H[i] = __float2bfloat16(0.f);
        g_h0L[i] = __float2bfloat16(0.f);
        g_c[i] = 0.f;
    }
    if (i < (MPAD - TT * BB) * HH) {
        size_t p = (size_t)TT * BB * HH + i;
        g_hsH[p] = __float2bfloat16(0.f);
        g_hsL[p] = __float2bfloat16(0.f);
    }
}

// fp32 -> bf16 hi/lo; 2 independent float4 per thread (MLP=2)
__global__ void k_conv(const float4* __restrict__ S, uint2* __restrict__ H,
                       uint2* __restrict__ L, int n4) {
    int i = blockIdx.x * blockDim.x + threadIdx.x;
    int half = n4 >> 1;
    if (i >= half) return;
    float4 v0 = S[i];
    float4 v1 = S[i + half];
    uint2 h0, l0, h1, l1;
    split2(v0.x, v0.y, h0.x, l0.x);
    split2(v0.z, v0.w, h0.y, l0.y);
    split2(v1.x, v1.y, h1.x, l1.x);
    split2(v1.z, v1.w, h1.y, l1.y);
    H[i] = h0; L[i] = l0;
    H[i + half] = h1; L[i + half] = l1;
}

// ctx[b,h] = sum_l features[b,l,h]; grid (64 batches, 4 h-chunks)
__global__ void k_ctx(const float* __restrict__ features) {
    int b = blockIdx.x;
    int h = blockIdx.y * 256 + threadIdx.x;
    const float* p = features + (size_t)b * 64 * HH + h;
    float s = 0.f;
#pragma unroll 8
    for (int l = 0; l < 64; l++) s += p[(size_t)l * HH];
    bf hi = __float2bfloat16(s);
    g_ctxH[b * HH + h] = hi;
    g_ctxL[b * HH + h] = __float2bfloat16(s - __bfloat162float(hi));
}

__global__ void k_emb(const float* __restrict__ embed, const int* __restrict__ captions) {
    int v = blockIdx.x * blockDim.x + threadIdx.x;
    int m = v >> 7;
    int e4 = (v & 127) << 2;
    int t = m / 64, b = m % 64;
    int cap = captions[b * 32 + t];
    float4 val = *(const float4*)(embed + (size_t)cap * EE + e4);
    uint2 h, l;
    split2(val.x, val.y, h.x, l.x);
    split2(val.z, val.w, h.y, l.y);
    ((uint2*)g_embH)[((size_t)m * EE + e4) >> 2] = h;
    ((uint2*)g_embL)[((size_t)m * EE + e4) >> 2] = l;
}

// ---------------------------------------------------------------------------
// mma.sync bf16x3 GEMM for gbias / gx (BM=64, BN=128, 2-stage). Proven config.
template<int MODE>
__global__ __launch_bounds__(256) void k_mm(
    const bf* __restrict__ AH, const bf* __restrict__ AL, int lda,
    const bf* __restrict__ BH, const bf* __restrict__ BL, int ldb,
    float* __restrict__ C, int ldc, int K,
    const float* __restrict__ bias1, const float* __restrict__ bias2,
    const float* __restrict__ addM)
{
    __shared__ unsigned AsH[2][64][12], AsL[2][64][12];
    __shared__ unsigned BsH[2][128][12], BsL[2][128][12];
    const int tid = threadIdx.x;
    const int wid = tid >> 5, lane = tid & 31, g = lane >> 2, tig = lane & 3;
    const int wm = (wid & 1) * 32, wn = (wid >> 1) * 32;
    const int bm = blockIdx.y * 64, bn = blockIdx.x * 128;

    const int arow = tid >> 2, asel = (tid >> 1) & 1, achk = tid & 1;
    const bf* aSrc = (asel ? AL : AH) + (size_t)(bm + arow) * lda + achk * 8;
    unsigned aD[2] = { s2u(&(asel ? AsL : AsH)[0][arow][achk * 4]),
                       s2u(&(asel ? AsL : AsH)[1][arow][achk * 4]) };
    const int b0r = tid >> 2, b0s = (tid >> 1) & 1, b0c = tid & 1;
    const int id1 = tid + 256;
    const int b1r = id1 >> 2, b1s = (id1 >> 1) & 1, b1c = id1 & 1;
    const bf* bSrc0 = (b0s ? BL : BH) + (size_t)(bn + b0r) * ldb + b0c * 8;
    const bf* bSrc1 = (b1s ? BL : BH) + (size_t)(bn + b1r) * ldb + b1c * 8;
    unsigned b0D[2] = { s2u(&(b0s ? BsL : BsH)[0][b0r][b0c * 4]),
                        s2u(&(b0s ? BsL : BsH)[1][b0r][b0c * 4]) };
    unsigned b1D[2] = { s2u(&(b1s ? BsL : BsH)[0][b1r][b1c * 4]),
                        s2u(&(b1s ? BsL : BsH)[1][b1r][b1c * 4]) };

    float acc[2][4][4] = {};
    CP16(aD[0], aSrc); CP16(b0D[0], bSrc0); CP16(b1D[0], bSrc1); CP_COMMIT();

    const int KT = K >> 4;
    for (int kt = 0; kt < KT; kt++) {
        const int cur = kt & 1, nxt = cur ^ 1;
        CP_WAIT0();
        __syncthreads();
        if (kt + 1 < KT) {
            CP16(aD[nxt], aSrc + (kt + 1) * 16);
            CP16(b0D[nxt], bSrc0 + (kt + 1) * 16);
            CP16(b1D[nxt], bSrc1 + (kt + 1) * 16);
            CP_COMMIT();
        }
        unsigned afH[2][4], afL[2][4], bfH[4][2], bfL[4][2];
#pragma unroll
        for (int mt = 0; mt < 2; mt++) {
            int r = wm + mt * 16 + g;
            afH[mt][0] = AsH[cur][r][tig];     afH[mt][1] = AsH[cur][r + 8][tig];
            afH[mt][2] = AsH[cur][r][tig + 4]; afH[mt][3] = AsH[cur][r + 8][tig + 4];
            afL[mt][0] = AsL[cur][r][tig];     afL[mt][1] = AsL[cur][r + 8][tig];
            afL[mt][2] = AsL[cur][r][tig + 4]; afL[mt][3] = AsL[cur][r + 8][tig + 4];
        }
#pragma unroll
        for (int nt = 0; nt < 4; nt++) {
            int n = wn + nt * 8 + g;
            bfH[nt][0] = BsH[cur][n][tig]; bfH[nt][1] = BsH[cur][n][tig + 4];
            bfL[nt][0] = BsL[cur][n][tig]; bfL[nt][1] = BsL[cur][n][tig + 4];
        }
#pragma unroll
        for (int mt = 0; mt < 2; mt++)
#pragma unroll
            for (int nt = 0; nt < 4; nt++) {
                mma_bf16(acc[mt][nt], afL[mt], bfH[nt]);
                mma_bf16(acc[mt][nt], afH[mt], bfL[nt]);
                mma_bf16(acc[mt][nt], afH[mt], bfH[nt]);
            }
    }

#pragma unroll
    for (int mt = 0; mt < 2; mt++) {
#pragma unroll
        for (int nt = 0; nt < 4; nt++) {
            int r0 = bm + wm + mt * 16 + g, r1 = r0 + 8;
            int n0 = bn + wn + nt * 8 + 2 * tig;
            float2 v01 = make_float2(acc[mt][nt][0], acc[mt][nt][1]);
            float2 v23 = make_float2(acc[mt][nt][2], acc[mt][nt][3]);
            if (MODE == 0) {
                float2 x = *(const float2*)(bias1 + n0);
                float2 y = *(const float2*)(bias2 + n0);
                v01.x += x.x + y.x; v01.y += x.y + y.y;
                v23.x += x.x + y.x; v23.y += x.y + y.y;
            }
            if (MODE == 1) {
                float2 x = *(const float2*)(addM + (size_t)(r0 & 63) * GG + n0);
                float2 y = *(const float2*)(addM + (size_t)(r1 & 63) * GG + n0);
                v01.x += x.x; v01.y += x.y;
                v23.x += y.x; v23.y += y.y;
            }
            *(float2*)(C + (size_t)r0 * ldc + n0) = v01;
            *(float2*)(C + (size_t)r1 * ldc + n0) = v23;
        }
    }
}

// ---------------------------------------------------------------------------
// Recurrent step, 3-stage pipeline (round-10 proven).
#define ST_W 2304

__global__ __launch_bounds__(256) void k_step(const bf* __restrict__ AH_,
                                              const bf* __restrict__ AL_, int t) {
    __shared__ unsigned sm[3 * ST_W];
    __shared__ float sg[64][33];
    const int tid = threadIdx.x;
    const int wid = tid >> 5, lane = tid & 31, g = lane >> 2, tig = lane & 3;
    const int wm = (wid & 1) * 32, wn = (wid >> 1) * 8;
    const int jj0 = blockIdx.x * 8;

    const bf* asrc;
    int acw;
    {
        int row = tid >> 2, sel = (tid >> 1) & 1, chunk = tid & 1;
        asrc = (sel ? AL_ : AH_) + (size_t)row * HH + chunk * 8;
        acw = sel * 768 + row * 12 + chunk * 4;
    }
    const bf* bsrc = nullptr;
    int bcw = 0;
    if (tid < 128) {
        int br = tid >> 2, bs = (tid >> 1) & 1, bc = tid & 1;
        int wrow = (br >> 3) * HH + jj0 + (br & 7);
        bsrc = (bs ? g_WhhL : g_WhhH) + (size_t)wrow * HH + bc * 8;
        bcw = 1536 + bs * 384 + br * 12 + bc * 4;
    }

    float acc[2][4] = {};
#pragma unroll
    for (int s = 0; s < 2; s++) {
        CP16(s2u(&sm[s * ST_W + acw]), asrc + s * 16);
        if (tid < 128) CP16(s2u(&sm[s * ST_W + bcw]), bsrc + s * 16);
        CP_COMMIT();
    }

    const int KT = HH >> 4;
    int buf = 0;
    for (int kt = 0; kt < KT; kt++) {
        CP_WAIT1();
        __syncthreads();
        if (kt + 2 < KT) {
            int s = (buf + 2) % 3;
            CP16(s2u(&sm[s * ST_W + acw]), asrc + (kt + 2) * 16);
            if (tid < 128) CP16(s2u(&sm[s * ST_W + bcw]), bsrc + (kt + 2) * 16);
            CP_COMMIT();
        } else {
            CP_COMMIT();
        }

        const unsigned* AHs = sm + buf * ST_W;
        const unsigned* ALs = AHs + 768;
        const unsigned* BHs = AHs + 1536;
        const unsigned* BLs = AHs + 1920;

        unsigned afH[2][4], afL[2][4], bfH[2], bfL[2];
#pragma unroll
        for (int mt = 0; mt < 2; mt++) {
            int r = (wm + mt * 16 + g) * 12;
            afH[mt][0] = AHs[r + tig];     afH[mt][1] = AHs[r + 96 + tig];
            afH[mt][2] = AHs[r + tig + 4]; afH[mt][3] = AHs[r + 96 + tig + 4];
            afL[mt][0] = ALs[r + tig];     afL[mt][1] = ALs[r + 96 + tig];
            afL[mt][2] = ALs[r + tig + 4]; afL[mt][3] = ALs[r + 96 + tig + 4];
        }
        int n = (wn + g) * 12;
        bfH[0] = BHs[n + tig]; bfH[1] = BHs[n + tig + 4];
        bfL[0] = BLs[n + tig]; bfL[1] = BLs[n + tig + 4];
#pragma unroll
        for (int mt = 0; mt < 2; mt++) {
            mma_bf16(acc[mt], afL[mt], bfH);
            mma_bf16(acc[mt], afH[mt], bfL);
            mma_bf16(acc[mt], afH[mt], bfH);
        }
        buf = (buf + 1) % 3;
    }

#pragma unroll
    for (int mt = 0; mt < 2; mt++)
#pragma unroll
        for (int q = 0; q < 4; q++) {
            int r = wm + mt * 16 + g + ((q >> 1) * 8);
            int j = wn + 2 * tig + (q & 1);
            sg[r][j] = acc[mt][q];
        }
    __syncthreads();

    const float* __restrict__ gx = g_gx + (size_t)t * 64 * GG;
    for (int u = tid; u < 512; u += 256) {
        int b = u >> 3, hh = u & 7;
        size_t gbase = (size_t)b * GG + jj0 + hh;
        float gi = sg[b][0 * 8 + hh] + gx[gbase];
        float gf = sg[b][1 * 8 + hh] + gx[gbase + HH];
        float gg = sg[b][2 * 8 + hh] + gx[gbase + 2 * HH];
        float go = sg[b][3 * 8 + hh] + gx[gbase + 3 * HH];
        int ci = b * HH + jj0 + hh;
        float cOld = g_c[ci];
        float si = 1.f / (1.f + expf(-gi));
        float sf = 1.f / (1.f + expf(-gf));
        float so = 1.f / (1.f + expf(-go));
        float cN = sf * cOld + si * tanhf(gg);
        float hN = so * tanhf(cN);
        g_c[ci] = cN;
        size_t hidx = ((size_t)t * 64 + b) * HH + jj0 + hh;
        bf hb = __float2bfloat16(hN);
        g_hsH[hidx] = hb;
        g_hsL[hidx] = __float2bfloat16(hN - __bfloat162float(hb));
    }
}

// ---------------------------------------------------------------------------
// Logits GEMM: BM=128, BN=128, BK=16, 8 warps (4Mx2N), warp 32x64, 3-stage.
#define LG_STG 6144
#define SMEM_LG3 (3 * LG_STG * 4)    // 72 KB

__global__ __launch_bounds__(256, 2) void k_logits3(const float* __restrict__ lin_b,
                                                    float* __restrict__ out) {
    extern __shared__ unsigned sm[];
    const int tid = threadIdx.x;
    const int wid = tid >> 5, lane = tid & 31, g = lane >> 2, tig = lane & 3;
    const int wm = (wid & 3) * 32, wn = (wid >> 2) * 64;
    const int bm = blockIdx.x * 128, bn = blockIdx.y * 128;

    const bf* csrc[4];
    int cword[4];
#pragma unroll
    for (int q = 0; q < 4; q++) {
        int i = tid + q * 256;
        int row = (i >> 2) & 127, sel = (i >> 1) & 1, chunk = i & 1;
        if (i < 512) {
            csrc[q] = (sel ? g_hsL : g_hsH) + (size_t)(bm + row) * HH + chunk * 8;
            cword[q] = sel * 1536 + row * 12 + chunk * 4;
        } else {
            csrc[q] = (sel ? g_linWL : g_linWH) + (size_t)(bn + row) * HH + chunk * 8;
            cword[q] = 3072 + sel * 1536 + row * 12 + chunk * 4;
        }
    }

    float acc[2][8][4] = {};

#pragma unroll
    for (int s = 0; s < 2; s++) {
#pragma unroll
        for (int q = 0; q < 4; q++)
            CP16(s2u(&sm[s * LG_STG + cword[q]]), csrc[q] + s * 16);
        CP_COMMIT();
    }

    const int KT = HH >> 4;
    int buf = 0;
    for (int kt = 0; kt < KT; kt++) {
        CP_WAIT1();
        __syncthreads();
        if (kt + 2 < KT) {
            int s = (buf + 2) % 3;
#pragma unroll
            for (int q = 0; q < 4; q++)
                CP16(s2u(&sm[s * LG_STG + cword[q]]), csrc[q] + (kt + 2) * 16);
            CP_COMMIT();
        } else {
            CP_COMMIT();
        }

        const unsigned* AHs = sm + buf * LG_STG;
        const unsigned* ALs = AHs + 1536;
        const unsigned* BHs = AHs + 3072;
        const unsigned* BLs = AHs + 4608;

        unsigned aH[2][4], aL[2][4];
#pragma unroll
        for (int mt = 0; mt < 2; mt++) {
            int r = (wm + mt * 16 + g) * 12;
            aH[mt][0] = AHs[r + tig];     aH[mt][1] = AHs[r + 96 + tig];
            aH[mt][2] = AHs[r + tig + 4]; aH[mt][3] = AHs[r + 96 + tig + 4];
            aL[mt][0] = ALs[r + tig];     aL[mt][1] = ALs[r + 96 + tig];
            aL[mt][2] = ALs[r + tig + 4]; aL[mt][3] = ALs[r + 96 + tig + 4];
        }
#pragma unroll
        for (int nt = 0; nt < 8; nt++) {
            int n = (wn + nt * 8 + g) * 12;
            unsigned bH[2], bL[2];
            bH[0] = BHs[n + tig]; bH[1] = BHs[n + tig + 4];
            bL[0] = BLs[n + tig]; bL[1] = BLs[n + tig + 4];
#pragma unroll
            for (int mt = 0; mt < 2; mt++) {
                mma_bf16(acc[mt][nt], aL[mt], bH);
                mma_bf16(acc[mt][nt], aH[mt], bL);
                mma_bf16(acc[mt][nt], aH[mt], bH);
            }
        }
        buf = (buf + 1) % 3;
    }

#pragma unroll
    for (int mt = 0; mt < 2; mt++) {
#pragma unroll
        for (int q2 = 0; q2 < 2; q2++) {
            int m = bm + wm + mt * 16 + g + q2 * 8;
            if (m >= TT * BB) continue;
            float* orow = out + (size_t)m * VV + bn;
#pragma unroll
            for (int nt = 0; nt < 8; nt++) {
                int n0 = wn + nt * 8 + 2 * tig;
                float2 bb = *(const float2*)(lin_b + bn + n0);
                float2 v = make_float2(acc[mt][nt][q2 * 2] + bb.x,
                                       acc[mt][nt][q2 * 2 + 1] + bb.y);
                *(float2*)(orow + n0) = v;
            }
        }
    }
}

// ---------------------------------------------------------------------------
extern "C" void kernel_launch(void* const* d_in, const int* in_sizes, int n_in,
                              void* d_out, int out_size) {
    const float* features = (const float*)d_in[0];
    const int*   captions = (const int*)d_in[1];
    const float* embed    = (const float*)d_in[3];
    const float* W_ih     = (const float*)d_in[4];
    const float* W_hh     = (const float*)d_in[5];
    const float* b_ih     = (const float*)d_in[6];
    const float* b_hh     = (const float*)d_in[7];
    const float* lin_W    = (const float*)d_in[10];
    const float* lin_b    = (const float*)d_in[11];
    float* out = (float*)d_out;

    bf *p_linWH, *p_linWL, *p_WihH, *p_WihL, *p_WhhH, *p_WhhL;
    bf *p_ctxH, *p_ctxL, *p_embH, *p_embL, *p_hsH, *p_hsL, *p_h0H, *p_h0L;
    float *p_gbias, *p_gx;
    cudaGetSymbolAddress((void**)&p_linWH, g_linWH);
    cudaGetSymbolAddress((void**)&p_linWL, g_linWL);
    cudaGetSymbolAddress((void**)&p_WihH, g_WihH);
    cudaGetSymbolAddress((void**)&p_WihL, g_WihL);
    cudaGetSymbolAddress((void**)&p_WhhH, g_WhhH);
    cudaGetSymbolAddress((void**)&p_WhhL, g_WhhL);
    cudaGetSymbolAddress((void**)&p_ctxH, g_ctxH);
    cudaGetSymbolAddress((void**)&p_ctxL, g_ctxL);
    cudaGetSymbolAddress((void**)&p_embH, g_embH);
    cudaGetSymbolAddress((void**)&p_embL, g_embL);
    cudaGetSymbolAddress((void**)&p_hsH, g_hsH);
    cudaGetSymbolAddress((void**)&p_hsL, g_hsL);
    cudaGetSymbolAddress((void**)&p_h0H, g_h0H);
    cudaGetSymbolAddress((void**)&p_h0L, g_h0L);
    cudaGetSymbolAddress((void**)&p_gbias, g_gbias);
    cudaGetSymbolAddress((void**)&p_gx, g_gx);

    cudaFuncSetAttribute(k_logits3, cudaFuncAttributeMaxDynamicSharedMemorySize, SMEM_LG3);

    // one-time side-stream + events (no device memory involved)
    static cudaStream_t s2 = nullptr;
    static cudaEvent_t evF = nullptr, evJ = nullptr;
    if (!s2) {
        cudaStreamCreateWithFlags(&s2, cudaStreamNonBlocking);
        cudaEventCreateWithFlags(&evF, cudaEventDisableTiming);
        cudaEventCreateWithFlags(&evJ, cudaEventDisableTiming);
    }

    k_init<<<(BB * HH + 255) / 256, 256>>>();
    int n4;
    n4 = GG * 1536 / 4;
    k_conv<<<(n4 / 2 + 255) / 256, 256>>>((const float4*)W_ih, (uint2*)p_WihH, (uint2*)p_WihL, n4);
    n4 = GG * HH / 4;
    k_conv<<<(n4 / 2 + 255) / 256, 256>>>((const float4*)W_hh, (uint2*)p_WhhH, (uint2*)p_WhhL, n4);
    k_ctx<<<dim3(BB, 4), 256>>>(features);
    k_emb<<<(TT * BB * EE / 4 + 255) / 256, 256>>>(embed, captions);

    // Fork: lin_W hi/lo conversion runs on side stream, overlapped with
    // gbias + gx + the 31 latency-bound step launches (DRAM mostly idle there).
    cudaEventRecord(evF, 0);
    cudaStreamWaitEvent(s2, evF, 0);
    n4 = VV * HH / 4;
    k_conv<<<(n4 / 2 + 255) / 256, 256, 0, s2>>>((const float4*)lin_W,
                                                 (uint2*)p_linWH, (uint2*)p_linWL, n4);
    cudaEventRecord(evJ, s2);

    k_mm<0><<<dim3(GG / 128, 1), 256>>>(p_ctxH, p_ctxL, HH,
                                        p_WihH + 512, p_WihL + 512, 1536,
                                        p_gbias, GG, HH, b_ih, b_hh, nullptr);
    k_mm<1><<<dim3(GG / 128, TT), 256>>>(p_embH, p_embL, EE,
                                         p_WihH, p_WihL, 1536,
                                         p_gx, GG, EE, nullptr, nullptr, p_gbias);
    for (int t = 0; t < TT; t++) {
        const bf* AH = t ? p_hsH + (size_t)(t - 1) * BB * HH : p_h0H;
        const bf* AL = t ? p_hsL + (size_t)(t - 1) * BB * HH : p_h0L;
        k_step<<<128, 256>>>(AH, AL, t);
    }
    // Join: logits needs the converted lin_W planes.
    cudaStreamWaitEvent(0, evJ, 0);
    k_logits3<<<dim3(MPAD / 128, VV / 128), 256, SMEM_LG3>>>(lin_b, out);
}

// round 14
// speedup vs baseline: 1.5268x; 1.0418x over previous
#include <cuda_runtime.h>
#include <cuda_bf16.h>
#include <math.h>
#include <stdint.h>

#define BB 64
#define TT 31
#define EE 512
#define HH 1024
#define GG 4096
#define VV 32000
#define MPAD 2048
typedef __nv_bfloat16 bf;

__device__ __align__(16) bf g_WihH[(size_t)GG * 1536], g_WihL[(size_t)GG * 1536];
__device__ __align__(16) bf g_WhhH[(size_t)GG * HH], g_WhhL[(size_t)GG * HH];
__device__ __align__(16) bf g_ctxH[BB * HH], g_ctxL[BB * HH];
__device__ __align__(16) bf g_embH[(size_t)TT * BB * EE], g_embL[(size_t)TT * BB * EE];
__device__ __align__(16) bf g_hsH[(size_t)MPAD * HH], g_hsL[(size_t)MPAD * HH];
__device__ __align__(16) bf g_h0H[BB * HH], g_h0L[BB * HH];
__device__ float g_gbias[BB * GG];
__device__ float g_gx[(size_t)TT * BB * GG];
__device__ float g_c[BB * HH];

// ---------------------------------------------------------------------------
#define CP16(dst, src) asm volatile("cp.async.ca.shared.global [%0], [%1], 16;" :: "r"(dst), "l"(src) : "memory")
#define CP_COMMIT() asm volatile("cp.async.commit_group;" ::: "memory")
#define CP_WAIT0() asm volatile("cp.async.wait_group 0;" ::: "memory")
#define CP_WAIT1() asm volatile("cp.async.wait_group 1;" ::: "memory")

__device__ __forceinline__ unsigned s2u(const void* p) {
    return (unsigned)__cvta_generic_to_shared(p);
}
__device__ __forceinline__ void mma_bf16(float c[4], const unsigned a[4], const unsigned b[2]) {
    asm("mma.sync.aligned.m16n8k16.row.col.f32.bf16.bf16.f32 "
        "{%0,%1,%2,%3},{%4,%5,%6,%7},{%8,%9},{%0,%1,%2,%3};"
        : "+f"(c[0]), "+f"(c[1]), "+f"(c[2]), "+f"(c[3])
        : "r"(a[0]), "r"(a[1]), "r"(a[2]), "r"(a[3]), "r"(b[0]), "r"(b[1]));
}
__device__ __forceinline__ void split2(float x, float y, unsigned& hi, unsigned& lo) {
    bf hx = __float2bfloat16(x), hy = __float2bfloat16(y);
    __nv_bfloat162 H = __halves2bfloat162(hx, hy);
    __nv_bfloat162 L = __halves2bfloat162(__float2bfloat16(x - __bfloat162float(hx)),
                                          __float2bfloat16(y - __bfloat162float(hy)));
    hi = *(unsigned*)&H;
    lo = *(unsigned*)&L;
}

// ---------------------------------------------------------------------------
__global__ void k_init() {
    int i = blockIdx.x * blockDim.x + threadIdx.x;
    if (i < BB * HH) {
        g_h0H[i] = __float2bfloat16(0.f);
        g_h0L[i] = __float2bfloat16(0.f);
        g_c[i] = 0.f;
    }
    if (i < (MPAD - TT * BB) * HH) {
        size_t p = (size_t)TT * BB * HH + i;
        g_hsH[p] = __float2bfloat16(0.f);
        g_hsL[p] = __float2bfloat16(0.f);
    }
}

// fp32 -> bf16 hi/lo; 2 independent float4 per thread (MLP=2)
__global__ void k_conv(const float4* __restrict__ S, uint2* __restrict__ H,
                       uint2* __restrict__ L, int n4) {
    int i = blockIdx.x * blockDim.x + threadIdx.x;
    int half = n4 >> 1;
    if (i >= half) return;
    float4 v0 = S[i];
    float4 v1 = S[i + half];
    uint2 h0, l0, h1, l1;
    split2(v0.x, v0.y, h0.x, l0.x);
    split2(v0.z, v0.w, h0.y, l0.y);
    split2(v1.x, v1.y, h1.x, l1.x);
    split2(v1.z, v1.w, h1.y, l1.y);
    H[i] = h0; L[i] = l0;
    H[i + half] = h1; L[i + half] = l1;
}

// ctx[b,h] = sum_l features[b,l,h]; grid (64 batches, 4 h-chunks)
__global__ void k_ctx(const float* __restrict__ features) {
    int b = blockIdx.x;
    int h = blockIdx.y * 256 + threadIdx.x;
    const float* p = features + (size_t)b * 64 * HH + h;
    float s = 0.f;
#pragma unroll 8
    for (int l = 0; l < 64; l++) s += p[(size_t)l * HH];
    bf hi = __float2bfloat16(s);
    g_ctxH[b * HH + h] = hi;
    g_ctxL[b * HH + h] = __float2bfloat16(s - __bfloat162float(hi));
}

__global__ void k_emb(const float* __restrict__ embed, const int* __restrict__ captions) {
    int v = blockIdx.x * blockDim.x + threadIdx.x;
    int m = v >> 7;
    int e4 = (v & 127) << 2;
    int t = m / 64, b = m % 64;
    int cap = captions[b * 32 + t];
    float4 val = *(const float4*)(embed + (size_t)cap * EE + e4);
    uint2 h, l;
    split2(val.x, val.y, h.x, l.x);
    split2(val.z, val.w, h.y, l.y);
    ((uint2*)g_embH)[((size_t)m * EE + e4) >> 2] = h;
    ((uint2*)g_embL)[((size_t)m * EE + e4) >> 2] = l;
}

// ---------------------------------------------------------------------------
// mma.sync bf16x3 GEMM for gbias / gx (BM=64, BN=128, 2-stage). Proven config.
template<int MODE>
__global__ __launch_bounds__(256) void k_mm(
    const bf* __restrict__ AH, const bf* __restrict__ AL, int lda,
    const bf* __restrict__ BH, const bf* __restrict__ BL, int ldb,
    float* __restrict__ C, int ldc, int K,
    const float* __restrict__ bias1, const float* __restrict__ bias2,
    const float* __restrict__ addM)
{
    __shared__ unsigned AsH[2][64][12], AsL[2][64][12];
    __shared__ unsigned BsH[2][128][12], BsL[2][128][12];
    const int tid = threadIdx.x;
    const int wid = tid >> 5, lane = tid & 31, g = lane >> 2, tig = lane & 3;
    const int wm = (wid & 1) * 32, wn = (wid >> 1) * 32;
    const int bm = blockIdx.y * 64, bn = blockIdx.x * 128;

    const int arow = tid >> 2, asel = (tid >> 1) & 1, achk = tid & 1;
    const bf* aSrc = (asel ? AL : AH) + (size_t)(bm + arow) * lda + achk * 8;
    unsigned aD[2] = { s2u(&(asel ? AsL : AsH)[0][arow][achk * 4]),
                       s2u(&(asel ? AsL : AsH)[1][arow][achk * 4]) };
    const int b0r = tid >> 2, b0s = (tid >> 1) & 1, b0c = tid & 1;
    const int id1 = tid + 256;
    const int b1r = id1 >> 2, b1s = (id1 >> 1) & 1, b1c = id1 & 1;
    const bf* bSrc0 = (b0s ? BL : BH) + (size_t)(bn + b0r) * ldb + b0c * 8;
    const bf* bSrc1 = (b1s ? BL : BH) + (size_t)(bn + b1r) * ldb + b1c * 8;
    unsigned b0D[2] = { s2u(&(b0s ? BsL : BsH)[0][b0r][b0c * 4]),
                        s2u(&(b0s ? BsL : BsH)[1][b0r][b0c * 4]) };
    unsigned b1D[2] = { s2u(&(b1s ? BsL : BsH)[0][b1r][b1c * 4]),
                        s2u(&(b1s ? BsL : BsH)[1][b1r][b1c * 4]) };

    float acc[2][4][4] = {};
    CP16(aD[0], aSrc); CP16(b0D[0], bSrc0); CP16(b1D[0], bSrc1); CP_COMMIT();

    const int KT = K >> 4;
    for (int kt = 0; kt < KT; kt++) {
        const int cur = kt & 1, nxt = cur ^ 1;
        CP_WAIT0();
        __syncthreads();
        if (kt + 1 < KT) {
            CP16(aD[nxt], aSrc + (kt + 1) * 16);
            CP16(b0D[nxt], bSrc0 + (kt + 1) * 16);
            CP16(b1D[nxt], bSrc1 + (kt + 1) * 16);
            CP_COMMIT();
        }
        unsigned afH[2][4], afL[2][4], bfH[4][2], bfL[4][2];
#pragma unroll
        for (int mt = 0; mt < 2; mt++) {
            int r = wm + mt * 16 + g;
            afH[mt][0] = AsH[cur][r][tig];     afH[mt][1] = AsH[cur][r + 8][tig];
            afH[mt][2] = AsH[cur][r][tig + 4]; afH[mt][3] = AsH[cur][r + 8][tig + 4];
            afL[mt][0] = AsL[cur][r][tig];     afL[mt][1] = AsL[cur][r + 8][tig];
            afL[mt][2] = AsL[cur][r][tig + 4]; afL[mt][3] = AsL[cur][r + 8][tig + 4];
        }
#pragma unroll
        for (int nt = 0; nt < 4; nt++) {
            int n = wn + nt * 8 + g;
            bfH[nt][0] = BsH[cur][n][tig]; bfH[nt][1] = BsH[cur][n][tig + 4];
            bfL[nt][0] = BsL[cur][n][tig]; bfL[nt][1] = BsL[cur][n][tig + 4];
        }
#pragma unroll
        for (int mt = 0; mt < 2; mt++)
#pragma unroll
            for (int nt = 0; nt < 4; nt++) {
                mma_bf16(acc[mt][nt], afL[mt], bfH[nt]);
                mma_bf16(acc[mt][nt], afH[mt], bfL[nt]);
                mma_bf16(acc[mt][nt], afH[mt], bfH[nt]);
            }
    }

#pragma unroll
    for (int mt = 0; mt < 2; mt++) {
#pragma unroll
        for (int nt = 0; nt < 4; nt++) {
            int r0 = bm + wm + mt * 16 + g, r1 = r0 + 8;
            int n0 = bn + wn + nt * 8 + 2 * tig;
            float2 v01 = make_float2(acc[mt][nt][0], acc[mt][nt][1]);
            float2 v23 = make_float2(acc[mt][nt][2], acc[mt][nt][3]);
            if (MODE == 0) {
                float2 x = *(const float2*)(bias1 + n0);
                float2 y = *(const float2*)(bias2 + n0);
                v01.x += x.x + y.x; v01.y += x.y + y.y;
                v23.x += x.x + y.x; v23.y += x.y + y.y;
            }
            if (MODE == 1) {
                float2 x = *(const float2*)(addM + (size_t)(r0 & 63) * GG + n0);
                float2 y = *(const float2*)(addM + (size_t)(r1 & 63) * GG + n0);
                v01.x += x.x; v01.y += x.y;
                v23.x += y.x; v23.y += y.y;
            }
            *(float2*)(C + (size_t)r0 * ldc + n0) = v01;
            *(float2*)(C + (size_t)r1 * ldc + n0) = v23;
        }
    }
}

// ---------------------------------------------------------------------------
// Recurrent step, 3-stage pipeline (round-10 proven).
#define ST_W 2304

__global__ __launch_bounds__(256) void k_step(const bf* __restrict__ AH_,
                                              const bf* __restrict__ AL_, int t) {
    __shared__ unsigned sm[3 * ST_W];
    __shared__ float sg[64][33];
    const int tid = threadIdx.x;
    const int wid = tid >> 5, lane = tid & 31, g = lane >> 2, tig = lane & 3;
    const int wm = (wid & 1) * 32, wn = (wid >> 1) * 8;
    const int jj0 = blockIdx.x * 8;

    const bf* asrc;
    int acw;
    {
        int row = tid >> 2, sel = (tid >> 1) & 1, chunk = tid & 1;
        asrc = (sel ? AL_ : AH_) + (size_t)row * HH + chunk * 8;
        acw = sel * 768 + row * 12 + chunk * 4;
    }
    const bf* bsrc = nullptr;
    int bcw = 0;
    if (tid < 128) {
        int br = tid >> 2, bs = (tid >> 1) & 1, bc = tid & 1;
        int wrow = (br >> 3) * HH + jj0 + (br & 7);
        bsrc = (bs ? g_WhhL : g_WhhH) + (size_t)wrow * HH + bc * 8;
        bcw = 1536 + bs * 384 + br * 12 + bc * 4;
    }

    float acc[2][4] = {};
#pragma unroll
    for (int s = 0; s < 2; s++) {
        CP16(s2u(&sm[s * ST_W + acw]), asrc + s * 16);
        if (tid < 128) CP16(s2u(&sm[s * ST_W + bcw]), bsrc + s * 16);
        CP_COMMIT();
    }

    const int KT = HH >> 4;
    int buf = 0;
    for (int kt = 0; kt < KT; kt++) {
        CP_WAIT1();
        __syncthreads();
        if (kt + 2 < KT) {
            int s = (buf + 2) % 3;
            CP16(s2u(&sm[s * ST_W + acw]), asrc + (kt + 2) * 16);
            if (tid < 128) CP16(s2u(&sm[s * ST_W + bcw]), bsrc + (kt + 2) * 16);
            CP_COMMIT();
        } else {
            CP_COMMIT();
        }

        const unsigned* AHs = sm + buf * ST_W;
        const unsigned* ALs = AHs + 768;
        const unsigned* BHs = AHs + 1536;
        const unsigned* BLs = AHs + 1920;

        unsigned afH[2][4], afL[2][4], bfH[2], bfL[2];
#pragma unroll
        for (int mt = 0; mt < 2; mt++) {
            int r = (wm + mt * 16 + g) * 12;
            afH[mt][0] = AHs[r + tig];     afH[mt][1] = AHs[r + 96 + tig];
            afH[mt][2] = AHs[r + tig + 4]; afH[mt][3] = AHs[r + 96 + tig + 4];
            afL[mt][0] = ALs[r + tig];     afL[mt][1] = ALs[r + 96 + tig];
            afL[mt][2] = ALs[r + tig + 4]; afL[mt][3] = ALs[r + 96 + tig + 4];
        }
        int n = (wn + g) * 12;
        bfH[0] = BHs[n + tig]; bfH[1] = BHs[n + tig + 4];
        bfL[0] = BLs[n + tig]; bfL[1] = BLs[n + tig + 4];
#pragma unroll
        for (int mt = 0; mt < 2; mt++) {
            mma_bf16(acc[mt], afL[mt], bfH);
            mma_bf16(acc[mt], afH[mt], bfL);
            mma_bf16(acc[mt], afH[mt], bfH);
        }
        buf = (buf + 1) % 3;
    }

#pragma unroll
    for (int mt = 0; mt < 2; mt++)
#pragma unroll
        for (int q = 0; q < 4; q++) {
            int r = wm + mt * 16 + g + ((q >> 1) * 8);
            int j = wn + 2 * tig + (q & 1);
            sg[r][j] = acc[mt][q];
        }
    __syncthreads();

    const float* __restrict__ gx = g_gx + (size_t)t * 64 * GG;
    for (int u = tid; u < 512; u += 256) {
        int b = u >> 3, hh = u & 7;
        size_t gbase = (size_t)b * GG + jj0 + hh;
        float gi = sg[b][0 * 8 + hh] + gx[gbase];
        float gf = sg[b][1 * 8 + hh] + gx[gbase + HH];
        float gg = sg[b][2 * 8 + hh] + gx[gbase + 2 * HH];
        float go = sg[b][3 * 8 + hh] + gx[gbase + 3 * HH];
        int ci = b * HH + jj0 + hh;
        float cOld = g_c[ci];
        float si = 1.f / (1.f + expf(-gi));
        float sf = 1.f / (1.f + expf(-gf));
        float so = 1.f / (1.f + expf(-go));
        float cN = sf * cOld + si * tanhf(gg);
        float hN = so * tanhf(cN);
        g_c[ci] = cN;
        size_t hidx = ((size_t)t * 64 + b) * HH + jj0 + hh;
        bf hb = __float2bfloat16(hN);
        g_hsH[hidx] = hb;
        g_hsL[hidx] = __float2bfloat16(hN - __bfloat162float(hb));
    }
}

// ---------------------------------------------------------------------------
// Logits GEMM: BM=128, BN=128, BK=16, 8 warps (4Mx2N), warp 32x64, 3-stage.
// B (lin_W) loaded as RAW FP32 and split to bf16 hi/lo in the mainloop —
// same bytes/slab as pre-split planes, but the 262MB conversion pass is gone.
// Stage layout (words): AH[128][12]@0 | AL@1536 | Bf32[128][20]@3072  (5632 w)
#define LG_STG 5632
#define SMEM_LG3 (3 * LG_STG * 4)    // 66 KB

__global__ __launch_bounds__(256, 2) void k_logits3(const float* __restrict__ linW,
                                                    const float* __restrict__ lin_b,
                                                    float* __restrict__ out) {
    extern __shared__ unsigned sm[];
    const int tid = threadIdx.x;
    const int wid = tid >> 5, lane = tid & 31, g = lane >> 2, tig = lane & 3;
    const int wm = (wid & 3) * 32, wn = (wid >> 2) * 64;
    const int bm = blockIdx.x * 128, bn = blockIdx.y * 128;

    // 1024 16B copy tasks / 256 threads = 4 each.
    // A tasks advance 32 B/slab (16 bf16); B tasks advance 64 B/slab (16 fp32).
    const char* csrc[4];
    int cword[4], cstep[4];
#pragma unroll
    for (int q = 0; q < 4; q++) {
        int i = tid + q * 256;
        if (i < 512) {
            int row = i >> 2, sel = (i >> 1) & 1, chunk = i & 1;
            csrc[q] = (const char*)((sel ? g_hsL : g_hsH) + (size_t)(bm + row) * HH + chunk * 8);
            cword[q] = sel * 1536 + row * 12 + chunk * 4;
            cstep[q] = 32;
        } else {
            int j = i - 512;
            int row = j >> 2, chunk = j & 3;
            csrc[q] = (const char*)(linW + (size_t)(bn + row) * HH + chunk * 4);
            cword[q] = 3072 + row * 20 + chunk * 4;
            cstep[q] = 64;
        }
    }

    float acc[2][8][4] = {};

#pragma unroll
    for (int s = 0; s < 2; s++) {
#pragma unroll
        for (int q = 0; q < 4; q++)
            CP16(s2u(&sm[s * LG_STG + cword[q]]), csrc[q] + s * cstep[q]);
        CP_COMMIT();
    }

    const int KT = HH >> 4;
    int buf = 0;
    for (int kt = 0; kt < KT; kt++) {
        CP_WAIT1();
        __syncthreads();
        if (kt + 2 < KT) {
            int s = (buf + 2) % 3;
#pragma unroll
            for (int q = 0; q < 4; q++)
                CP16(s2u(&sm[s * LG_STG + cword[q]]), csrc[q] + (kt + 2) * cstep[q]);
            CP_COMMIT();
        } else {
            CP_COMMIT();
        }

        const unsigned* AHs = sm + buf * LG_STG;
        const unsigned* ALs = AHs + 1536;
        const float* Bf = (const float*)(AHs + 3072);

        unsigned aH[2][4], aL[2][4];
#pragma unroll
        for (int mt = 0; mt < 2; mt++) {
            int r = (wm + mt * 16 + g) * 12;
            aH[mt][0] = AHs[r + tig];     aH[mt][1] = AHs[r + 96 + tig];
            aH[mt][2] = AHs[r + tig + 4]; aH[mt][3] = AHs[r + 96 + tig + 4];
            aL[mt][0] = ALs[r + tig];     aL[mt][1] = ALs[r + 96 + tig];
            aL[mt][2] = ALs[r + tig + 4]; aL[mt][3] = ALs[r + 96 + tig + 4];
        }
#pragma unroll
        for (int nt = 0; nt < 8; nt++) {
            int n = (wn + nt * 8 + g) * 20;
            float2 f0 = *(const float2*)(Bf + n + 2 * tig);
            float2 f1 = *(const float2*)(Bf + n + 2 * tig + 8);
            unsigned bH[2], bL[2];
            split2(f0.x, f0.y, bH[0], bL[0]);
            split2(f1.x, f1.y, bH[1], bL[1]);
#pragma unroll
            for (int mt = 0; mt < 2; mt++) {
                mma_bf16(acc[mt][nt], aL[mt], bH);
                mma_bf16(acc[mt][nt], aH[mt], bL);
                mma_bf16(acc[mt][nt], aH[mt], bH);
            }
        }
        buf = (buf + 1) % 3;
    }

#pragma unroll
    for (int mt = 0; mt < 2; mt++) {
#pragma unroll
        for (int q2 = 0; q2 < 2; q2++) {
            int m = bm + wm + mt * 16 + g + q2 * 8;
            if (m >= TT * BB) continue;
            float* orow = out + (size_t)m * VV + bn;
#pragma unroll
            for (int nt = 0; nt < 8; nt++) {
                int n0 = wn + nt * 8 + 2 * tig;
                float2 bb = *(const float2*)(lin_b + bn + n0);
                float2 v = make_float2(acc[mt][nt][q2 * 2] + bb.x,
                                       acc[mt][nt][q2 * 2 + 1] + bb.y);
                *(float2*)(orow + n0) = v;
            }
        }
    }
}

// ---------------------------------------------------------------------------
extern "C" void kernel_launch(void* const* d_in, const int* in_sizes, int n_in,
                              void* d_out, int out_size) {
    const float* features = (const float*)d_in[0];
    const int*   captions = (const int*)d_in[1];
    const float* embed    = (const float*)d_in[3];
    const float* W_ih     = (const float*)d_in[4];
    const float* W_hh     = (const float*)d_in[5];
    const float* b_ih     = (const float*)d_in[6];
    const float* b_hh     = (const float*)d_in[7];
    const float* lin_W    = (const float*)d_in[10];
    const float* lin_b    = (const float*)d_in[11];
    float* out = (float*)d_out;

    bf *p_WihH, *p_WihL, *p_WhhH, *p_WhhL;
    bf *p_ctxH, *p_ctxL, *p_embH, *p_embL, *p_hsH, *p_hsL, *p_h0H, *p_h0L;
    float *p_gbias, *p_gx;
    cudaGetSymbolAddress((void**)&p_WihH, g_WihH);
    cudaGetSymbolAddress((void**)&p_WihL, g_WihL);
    cudaGetSymbolAddress((void**)&p_WhhH, g_WhhH);
    cudaGetSymbolAddress((void**)&p_WhhL, g_WhhL);
    cudaGetSymbolAddress((void**)&p_ctxH, g_ctxH);
    cudaGetSymbolAddress((void**)&p_ctxL, g_ctxL);
    cudaGetSymbolAddress((void**)&p_embH, g_embH);
    cudaGetSymbolAddress((void**)&p_embL, g_embL);
    cudaGetSymbolAddress((void**)&p_hsH, g_hsH);
    cudaGetSymbolAddress((void**)&p_hsL, g_hsL);
    cudaGetSymbolAddress((void**)&p_h0H, g_h0H);
    cudaGetSymbolAddress((void**)&p_h0L, g_h0L);
    cudaGetSymbolAddress((void**)&p_gbias, g_gbias);
    cudaGetSymbolAddress((void**)&p_gx, g_gx);

    cudaFuncSetAttribute(k_logits3, cudaFuncAttributeMaxDynamicSharedMemorySize, SMEM_LG3);

    k_init<<<(BB * HH + 255) / 256, 256>>>();
    int n4;
    n4 = GG * 1536 / 4;
    k_conv<<<(n4 / 2 + 255) / 256, 256>>>((const float4*)W_ih, (uint2*)p_WihH, (uint2*)p_WihL, n4);
    n4 = GG * HH / 4;
    k_conv<<<(n4 / 2 + 255) / 256, 256>>>((const float4*)W_hh, (uint2*)p_WhhH, (uint2*)p_WhhL, n4);
    k_ctx<<<dim3(BB, 4), 256>>>(features);
    k_emb<<<(TT * BB * EE / 4 + 255) / 256, 256>>>(embed, captions);
    // gbias = ctx @ W_ih[:,512:]^T + b_ih + b_hh
    k_mm<0><<<dim3(GG / 128, 1), 256>>>(p_ctxH, p_ctxL, HH,
                                        p_WihH + 512, p_WihL + 512, 1536,
                                        p_gbias, GG, HH, b_ih, b_hh, nullptr);
    // gx = emb @ W_ih[:,:512]^T + gbias
    k_mm<1><<<dim3(GG / 128, TT), 256>>>(p_embH, p_embL, EE,
                                         p_WihH, p_WihL, 1536,
                                         p_gx, GG, EE, nullptr, nullptr, p_gbias);
    for (int t = 0; t < TT; t++) {
        const bf* AH = t ? p_hsH + (size_t)(t - 1) * BB * HH : p_h0H;
        const bf* AL = t ? p_hsL + (size_t)(t - 1) * BB * HH : p_h0L;
        k_step<<<128, 256>>>(AH, AL, t);
    }
    // logits = hs @ lin_W^T + lin_b  (fp32 B, in-loop split — no conversion pass)
    k_logits3<<<dim3(MPAD / 128, VV / 128), 256, SMEM_LG3>>>(lin_W, lin_b, out);
}